// round 10
// baseline (speedup 1.0000x reference)
#include <cuda_runtime.h>
#include <cuda_bf16.h>
#include <math.h>
#include <stdint.h>

#define BB 2
#define NN 512
#define CC 256
#define POOLP 7
#define NCLS 81
#define MROWS (BB*NN)          // 1024
#define K1 (CC*POOLP*POOLP)    // 12544
#define H1 1024
#define IMGSZ 1024.0f

// ---------------- scratch (device globals; no allocation allowed) ----------------
__device__ __nv_bfloat16 g_xhi[(size_t)MROWS * K1];
__device__ __nv_bfloat16 g_xlo[(size_t)MROWS * K1];
__device__ __nv_bfloat16 g_w1hi[(size_t)H1 * K1];
__device__ __nv_bfloat16 g_w1lo[(size_t)H1 * K1];
__device__ __nv_bfloat16 g_w2hi[(size_t)H1 * H1];
__device__ __nv_bfloat16 g_w2lo[(size_t)H1 * H1];
__device__ __nv_bfloat16 g_hhi[(size_t)MROWS * H1];
__device__ __nv_bfloat16 g_hlo[(size_t)MROWS * H1];
__device__ float g_part[(size_t)2 * MROWS * H1]; // split-K partials
__device__ float g_h[MROWS * H1];           // fc1 pre-BN (fp32)
__device__ float g_s[MROWS * H1];           // fc2 pre/post BN ("shared")
__device__ float g_stats[2 * H1];           // mean, var per feature
__device__ float g_mw1[NCLS * H1];          // MLP intermediate

// ================= PTX helpers (base-target only: sm_80-class) =================
__device__ __forceinline__ uint32_t smem_u32(const void* p) {
    uint32_t a;
    asm("{ .reg .u64 t; cvta.to.shared.u64 t, %1; cvt.u32.u64 %0, t; }" : "=r"(a) : "l"(p));
    return a;
}
__device__ __forceinline__ void cp_async16(uint32_t dst, const void* src) {
    asm volatile("cp.async.cg.shared.global [%0], [%1], 16;" :: "r"(dst), "l"(src) : "memory");
}
__device__ __forceinline__ void ldsm_x4(uint32_t* r, uint32_t addr) {
    asm volatile("ldmatrix.sync.aligned.m8n8.x4.shared.b16 {%0,%1,%2,%3}, [%4];"
                 : "=r"(r[0]), "=r"(r[1]), "=r"(r[2]), "=r"(r[3]) : "r"(addr));
}
__device__ __forceinline__ void mma16816(float* d, const uint32_t* a, const uint32_t* b) {
    asm volatile("mma.sync.aligned.m16n8k16.row.col.f32.bf16.bf16.f32 "
                 "{%0,%1,%2,%3}, {%4,%5,%6,%7}, {%8,%9}, {%0,%1,%2,%3};"
                 : "+f"(d[0]), "+f"(d[1]), "+f"(d[2]), "+f"(d[3])
                 : "r"(a[0]), "r"(a[1]), "r"(a[2]), "r"(a[3]), "r"(b[0]), "r"(b[1]));
}

// ================= mma.sync 3x-bf16 GEMM with split-K ==========================
// P[z][M,N] = A[M, z-th K slice] @ B[N, z-th K slice]^T  (no bias; reduce adds it)
// Requires M % 64 == 0, N % 128 == 0, Klen % 32 == 0.
#define MM_BM 64
#define MM_BN 128
#define MM_BK 32
#define MM_RSTRIDE 80                   // bytes per smem row (32 bf16 + 16B pad)
#define MM_ABYTES (MM_BM * MM_RSTRIDE)  // 5120
#define MM_BBYTES (MM_BN * MM_RSTRIDE)  // 10240
#define MM_BUF (2*MM_ABYTES + 2*MM_BBYTES)  // 30720
#define MM_SMEM (2*MM_BUF)                  // 61440

__global__ void __launch_bounds__(256)
gemm_mma3_kernel(const __nv_bfloat16* __restrict__ Ahi, const __nv_bfloat16* __restrict__ Alo,
                 const __nv_bfloat16* __restrict__ Bhi, const __nv_bfloat16* __restrict__ Blo,
                 float* __restrict__ P, int N, int Ktot, int Klen)
{
    extern __shared__ char smem[];
    uint32_t sb = smem_u32(smem);
    int tid = threadIdx.x;
    int wid = tid >> 5, lane = tid & 31;
    int rowBase = blockIdx.y * MM_BM;
    int colBase = blockIdx.x * MM_BN;
    int kStart  = blockIdx.z * Klen;
    float* Cpart = P + (size_t)blockIdx.z * MROWS * H1;
    int warp_m = wid >> 2;      // 0..1  -> 32 rows each (2 m-tiles of 16)
    int warp_n = wid & 3;       // 0..3  -> 32 cols each (4 n-tiles of 8)
    int m_base = warp_m * 32;
    int n_base = warp_n * 32;

    float acc[2][4][4];
    #pragma unroll
    for (int mt = 0; mt < 2; mt++)
        #pragma unroll
        for (int nt = 0; nt < 4; nt++)
            #pragma unroll
            for (int j = 0; j < 4; j++) acc[mt][nt][j] = 0.f;

    int nc = Klen / MM_BK;

    auto load_chunk = [&](int c, int p) {
        uint32_t base = sb + (uint32_t)p * MM_BUF;
        int k0 = kStart + c * MM_BK;
        #pragma unroll
        for (int i = 0; i < 2; i++) {                 // A: 512 x 16B segments
            int id = tid + i * 256;
            int t = id >> 8;                          // 0=hi 1=lo
            int s = id & 255;
            int r = s >> 2, cseg = s & 3;
            const __nv_bfloat16* src = (t ? Alo : Ahi) + (size_t)(rowBase + r) * Ktot + k0 + cseg * 8;
            cp_async16(base + (uint32_t)t * MM_ABYTES + (uint32_t)(r * MM_RSTRIDE + cseg * 16), src);
        }
        #pragma unroll
        for (int i = 0; i < 4; i++) {                 // B: 1024 x 16B segments
            int id = tid + i * 256;
            int t = id >> 9;
            int s = id & 511;
            int r = s >> 2, cseg = s & 3;
            const __nv_bfloat16* src = (t ? Blo : Bhi) + (size_t)(colBase + r) * Ktot + k0 + cseg * 8;
            cp_async16(base + 2 * MM_ABYTES + (uint32_t)t * MM_BBYTES + (uint32_t)(r * MM_RSTRIDE + cseg * 16), src);
        }
        asm volatile("cp.async.commit_group;" ::: "memory");
    };

    load_chunk(0, 0);

    for (int c = 0; c < nc; c++) {
        int p = c & 1;
        if (c + 1 < nc) {
            load_chunk(c + 1, (c + 1) & 1);
            asm volatile("cp.async.wait_group 1;" ::: "memory");
        } else {
            asm volatile("cp.async.wait_group 0;" ::: "memory");
        }
        __syncthreads();

        uint32_t abase = sb + (uint32_t)p * MM_BUF;
        uint32_t bbase = abase + 2 * MM_ABYTES;

        #pragma unroll
        for (int ks = 0; ks < 2; ks++) {
            uint32_t ahi[2][4], alo[2][4];
            {
                int arow = m_base + (lane & 15);
                uint32_t acol = (uint32_t)((ks * 16 + ((lane >> 4) << 3)) * 2);
                #pragma unroll
                for (int mt = 0; mt < 2; mt++) {
                    uint32_t addr = abase + (uint32_t)((arow + mt * 16) * MM_RSTRIDE) + acol;
                    ldsm_x4(ahi[mt], addr);
                    ldsm_x4(alo[mt], addr + MM_ABYTES);
                }
            }
            uint32_t bh[4][2], bl[4][2];
            {
                int brow = n_base + ((lane >= 16) ? 8 : 0) + (lane & 7);
                uint32_t bcol = (uint32_t)((ks * 16 + (((lane >> 3) & 1) << 3)) * 2);
                #pragma unroll
                for (int np = 0; np < 2; np++) {
                    uint32_t addr = bbase + (uint32_t)((brow + np * 16) * MM_RSTRIDE) + bcol;
                    uint32_t r4[4];
                    ldsm_x4(r4, addr);
                    bh[np*2][0] = r4[0]; bh[np*2][1] = r4[1];
                    bh[np*2+1][0] = r4[2]; bh[np*2+1][1] = r4[3];
                    ldsm_x4(r4, addr + MM_BBYTES);
                    bl[np*2][0] = r4[0]; bl[np*2][1] = r4[1];
                    bl[np*2+1][0] = r4[2]; bl[np*2+1][1] = r4[3];
                }
            }
            #pragma unroll
            for (int mt = 0; mt < 2; mt++)
                #pragma unroll
                for (int nt = 0; nt < 4; nt++) {
                    mma16816(acc[mt][nt], ahi[mt], bh[nt]);
                    mma16816(acc[mt][nt], ahi[mt], bl[nt]);
                    mma16816(acc[mt][nt], alo[mt], bh[nt]);
                }
        }
        __syncthreads();
    }

    // ---- epilogue: store partials ----
    int g = lane >> 2, t2 = (lane & 3) * 2;
    #pragma unroll
    for (int mt = 0; mt < 2; mt++) {
        int row0 = rowBase + m_base + mt * 16 + g;
        #pragma unroll
        for (int nt = 0; nt < 4; nt++) {
            int col = colBase + n_base + nt * 8 + t2;
            float2* p0 = reinterpret_cast<float2*>(&Cpart[(size_t)row0 * N + col]);
            float2* p1 = reinterpret_cast<float2*>(&Cpart[(size_t)(row0 + 8) * N + col]);
            *p0 = make_float2(acc[mt][nt][0], acc[mt][nt][1]);
            *p1 = make_float2(acc[mt][nt][2], acc[mt][nt][3]);
        }
    }
}

// ---------------- split-K reduce + bias: C = P0 + P1 + bias ----------------
__global__ void reduce_bias_kernel(const float* __restrict__ P, const float* __restrict__ bias,
                                   float* __restrict__ C, int MN, int N)
{
    int i = (blockIdx.x * blockDim.x + threadIdx.x) * 4;
    if (i >= MN) return;
    float4 a = *reinterpret_cast<const float4*>(&P[i]);
    float4 b = *reinterpret_cast<const float4*>(&P[(size_t)MROWS * H1 + i]);
    float4 bs = *reinterpret_cast<const float4*>(&bias[i % N]);
    float4 r;
    r.x = a.x + b.x + bs.x;
    r.y = a.y + b.y + bs.y;
    r.z = a.z + b.z + bs.z;
    r.w = a.w + b.w + bs.w;
    *reinterpret_cast<float4*>(&C[i]) = r;
}

// ---------------- ROI align -> bf16 hi/lo directly ----------------
__global__ void roi_align_kernel(const float* __restrict__ p2, const float* __restrict__ p3,
                                 const float* __restrict__ p4, const float* __restrict__ p5,
                                 const float* __restrict__ rois,
                                 __nv_bfloat16* __restrict__ Xhi, __nv_bfloat16* __restrict__ Xlo)
{
    int n = blockIdx.x;
    const float* roi = rois + (size_t)n * 4;
    float x1 = roi[0], y1 = roi[1], x2 = roi[2], y2 = roi[3];
    float area = (y2 - y1) * (x2 - x1);
    float lf = rintf(log2f(sqrtf(area) / 224.0f)) + 4.0f;   // half-to-even like jnp.round
    lf = fminf(fmaxf(lf, 2.0f), 5.0f);
    int lvl = (int)lf;

    const float* fm; int H;
    if (lvl == 2)      { fm = p2; H = 256; }
    else if (lvl == 3) { fm = p3; H = 128; }
    else if (lvl == 4) { fm = p4; H = 64;  }
    else               { fm = p5; H = 32;  }
    int W = H;

    float ny1 = y1 / IMGSZ, nx1 = x1 / IMGSZ, ny2 = y2 / IMGSZ, nx2 = x2 / IMGSZ;

    __shared__ int   s_y0[POOLP], s_y1[POOLP], s_x0[POOLP], s_x1[POOLP];
    __shared__ float s_ly[POOLP], s_lx[POOLP];

    int t = threadIdx.x;
    if (t < POOLP) {
        float g = (float)t / (float)(POOLP - 1);
        float ys = (ny1 + g * (ny2 - ny1)) * (float)(H - 1);
        float y0f = floorf(ys);
        s_ly[t] = ys - y0f;
        s_y0[t] = (int)fminf(fmaxf(y0f, 0.0f), (float)(H - 1));
        s_y1[t] = (int)fminf(fmaxf(y0f + 1.0f, 0.0f), (float)(H - 1));
    } else if (t < 2 * POOLP) {
        int j = t - POOLP;
        float g = (float)j / (float)(POOLP - 1);
        float xs = (nx1 + g * (nx2 - nx1)) * (float)(W - 1);
        float x0f = floorf(xs);
        s_lx[j] = xs - x0f;
        s_x0[j] = (int)fminf(fmaxf(x0f, 0.0f), (float)(W - 1));
        s_x1[j] = (int)fminf(fmaxf(x0f + 1.0f, 0.0f), (float)(W - 1));
    }
    __syncthreads();

    int HW = H * W;
    for (int idx = threadIdx.x; idx < K1; idx += blockDim.x) {
        int c  = idx / (POOLP * POOLP);
        int p  = idx % (POOLP * POOLP);
        int py = p / POOLP, px = p % POOLP;
        const float* plane = fm + (size_t)c * HW;
        float ly = s_ly[py], lx = s_lx[px];
        int y0 = s_y0[py], y1i = s_y1[py], x0 = s_x0[px], x1i = s_x1[px];
        float v00 = plane[y0  * W + x0 ];
        float v01 = plane[y0  * W + x1i];
        float v10 = plane[y1i * W + x0 ];
        float v11 = plane[y1i * W + x1i];
        float val = v00 * (1.0f - ly) * (1.0f - lx)
                  + v01 * (1.0f - ly) * lx
                  + v10 * ly * (1.0f - lx)
                  + v11 * ly * lx;
        __nv_bfloat16 h = __float2bfloat16(val);
        Xhi[(size_t)n * K1 + idx] = h;
        Xlo[(size_t)n * K1 + idx] = __float2bfloat16(val - __bfloat162float(h));
    }
}

// ---------------- fp32 -> (hi, lo) bf16 split ----------------
__global__ void cvt_pair_kernel(const float* __restrict__ src,
                                __nv_bfloat16* __restrict__ hi, __nv_bfloat16* __restrict__ lo, int n)
{
    int i = blockIdx.x * blockDim.x + threadIdx.x;
    if (i < n) {
        float v = src[i];
        __nv_bfloat16 h = __float2bfloat16(v);
        hi[i] = h;
        lo[i] = __float2bfloat16(v - __bfloat162float(h));
    }
}

// ---------------- fp32 tiled GEMM for small heads: C = A @ B^T + bias ----------------
#define BM 64
#define BN 64
#define BK 16
__global__ void gemm_abt_kernel(const float* __restrict__ A, const float* __restrict__ B,
                                const float* __restrict__ bias, float* __restrict__ C,
                                int M, int N, int K, int act)
{
    __shared__ float As[BK][BM];
    __shared__ float Bs[BK][BN];

    int tid = threadIdx.x;
    int tx = tid & 15;
    int ty = tid >> 4;
    int rowBase = blockIdx.y * BM;
    int colBase = blockIdx.x * BN;
    int lr = tid >> 2;
    int lk = (tid & 3) * 4;

    float acc[4][4] = {{0.f}};

    for (int k0 = 0; k0 < K; k0 += BK) {
        float4 av = make_float4(0.f, 0.f, 0.f, 0.f);
        int ar = rowBase + lr;
        if (ar < M) av = *reinterpret_cast<const float4*>(&A[(size_t)ar * K + k0 + lk]);
        As[lk + 0][lr] = av.x; As[lk + 1][lr] = av.y;
        As[lk + 2][lr] = av.z; As[lk + 3][lr] = av.w;

        float4 bv = make_float4(0.f, 0.f, 0.f, 0.f);
        int br = colBase + lr;
        if (br < N) bv = *reinterpret_cast<const float4*>(&B[(size_t)br * K + k0 + lk]);
        Bs[lk + 0][lr] = bv.x; Bs[lk + 1][lr] = bv.y;
        Bs[lk + 2][lr] = bv.z; Bs[lk + 3][lr] = bv.w;

        __syncthreads();

        #pragma unroll
        for (int k = 0; k < BK; k++) {
            float4 a = *reinterpret_cast<const float4*>(&As[k][ty * 4]);
            float4 b = *reinterpret_cast<const float4*>(&Bs[k][tx * 4]);
            float aa[4] = {a.x, a.y, a.z, a.w};
            float bb[4] = {b.x, b.y, b.z, b.w};
            #pragma unroll
            for (int i = 0; i < 4; i++)
                #pragma unroll
                for (int j = 0; j < 4; j++)
                    acc[i][j] = fmaf(aa[i], bb[j], acc[i][j]);
        }
        __syncthreads();
    }

    #pragma unroll
    for (int i = 0; i < 4; i++) {
        int row = rowBase + ty * 4 + i;
        if (row >= M) continue;
        #pragma unroll
        for (int j = 0; j < 4; j++) {
            int col = colBase + tx * 4 + j;
            if (col >= N) continue;
            float v = acc[i][j] + bias[col];
            if (act == 1) v = (v >= 0.f) ? v : 0.01f * v;
            C[(size_t)row * N + col] = v;
        }
    }
}

// ---------------- batch-norm stats ----------------
__global__ void bn_stats_kernel(const float* __restrict__ Hm, float* __restrict__ stats,
                                int M, int N)
{
    int col = blockIdx.x;
    int tid = threadIdx.x;
    float s = 0.f, s2 = 0.f;
    for (int r = tid; r < M; r += blockDim.x) {
        float v = Hm[(size_t)r * N + col];
        s += v; s2 += v * v;
    }
    __shared__ float sh[256], sh2[256];
    sh[tid] = s; sh2[tid] = s2;
    __syncthreads();
    for (int o = 128; o > 0; o >>= 1) {
        if (tid < o) { sh[tid] += sh[tid + o]; sh2[tid] += sh2[tid + o]; }
        __syncthreads();
    }
    if (tid == 0) {
        float m = sh[0] / (float)M;
        stats[col]     = m;
        stats[N + col] = sh2[0] / (float)M - m * m;
    }
}

// BN1: apply + relu, write bf16 hi/lo (feeds tensor GEMM2)
__global__ void bn_apply_relu_cvt_kernel(const float* __restrict__ Hm, const float* __restrict__ stats,
                                         const float* __restrict__ gam, const float* __restrict__ bet,
                                         __nv_bfloat16* __restrict__ hi, __nv_bfloat16* __restrict__ lo,
                                         int M, int N)
{
    int idx = blockIdx.x * blockDim.x + threadIdx.x;
    if (idx >= M * N) return;
    int col = idx % N;
    float m = stats[col], v = stats[N + col];
    float h = (Hm[idx] - m) * rsqrtf(v + 0.001f) * gam[col] + bet[col];
    h = fmaxf(h, 0.f);
    __nv_bfloat16 hh = __float2bfloat16(h);
    hi[idx] = hh;
    lo[idx] = __float2bfloat16(h - __bfloat162float(hh));
}

// BN2: apply + relu in-place fp32 (feeds fp32 heads)
__global__ void bn_apply_relu_kernel(float* __restrict__ Hm, const float* __restrict__ stats,
                                     const float* __restrict__ gam, const float* __restrict__ bet,
                                     int M, int N)
{
    int idx = blockIdx.x * blockDim.x + threadIdx.x;
    if (idx >= M * N) return;
    int col = idx % N;
    float m = stats[col], v = stats[N + col];
    float h = (Hm[idx] - m) * rsqrtf(v + 0.001f) * gam[col] + bet[col];
    Hm[idx] = fmaxf(h, 0.f);
}

// ---------------- softmax over 81 classes per row ----------------
__global__ void softmax_kernel(const float* __restrict__ logits, float* __restrict__ probs)
{
    int row = blockIdx.x;
    int t = threadIdx.x;   // 128 threads
    __shared__ float red[128];
    float v = (t < NCLS) ? logits[(size_t)row * NCLS + t] : -INFINITY;
    red[t] = v;
    __syncthreads();
    for (int o = 64; o > 0; o >>= 1) {
        if (t < o) red[t] = fmaxf(red[t], red[t + o]);
        __syncthreads();
    }
    float mx = red[0];
    __syncthreads();
    float e = (t < NCLS) ? expf(v - mx) : 0.f;
    red[t] = e;
    __syncthreads();
    for (int o = 64; o > 0; o >>= 1) {
        if (t < o) red[t] += red[t + o];
        __syncthreads();
    }
    if (t < NCLS) probs[(size_t)row * NCLS + t] = e / red[0];
}

// ---------------- launch ----------------
extern "C" void kernel_launch(void* const* d_in, const int* in_sizes, int n_in,
                              void* d_out, int out_size)
{
    const float* p2      = (const float*)d_in[0];
    const float* p3      = (const float*)d_in[1];
    const float* p4      = (const float*)d_in[2];
    const float* p5      = (const float*)d_in[3];
    const float* rois    = (const float*)d_in[4];
    const float* conv1_w = (const float*)d_in[5];
    const float* conv1_b = (const float*)d_in[6];
    const float* bn1_g   = (const float*)d_in[7];
    const float* bn1_b   = (const float*)d_in[8];
    const float* conv2_w = (const float*)d_in[9];
    const float* conv2_b = (const float*)d_in[10];
    const float* bn2_g   = (const float*)d_in[11];
    const float* bn2_b   = (const float*)d_in[12];
    const float* cls_w   = (const float*)d_in[13];
    const float* cls_b   = (const float*)d_in[14];
    const float* box_w   = (const float*)d_in[15];
    const float* box_b   = (const float*)d_in[16];
    const float* tf1_w   = (const float*)d_in[17];
    const float* tf1_b   = (const float*)d_in[18];
    const float* tf2_w   = (const float*)d_in[19];
    const float* tf2_b   = (const float*)d_in[20];
    float* out = (float*)d_out;

    static __nv_bfloat16 *xhi=nullptr,*xlo=nullptr,*w1hi=nullptr,*w1lo=nullptr,*w2hi=nullptr,*w2lo=nullptr,*hhi=nullptr,*hlo=nullptr;
    static float *hp=nullptr, *sp=nullptr, *st=nullptr, *mw=nullptr, *pp=nullptr;
    if (!hp) {
        cudaGetSymbolAddress((void**)&xhi, g_xhi);
        cudaGetSymbolAddress((void**)&xlo, g_xlo);
        cudaGetSymbolAddress((void**)&w1hi, g_w1hi);
        cudaGetSymbolAddress((void**)&w1lo, g_w1lo);
        cudaGetSymbolAddress((void**)&w2hi, g_w2hi);
        cudaGetSymbolAddress((void**)&w2lo, g_w2lo);
        cudaGetSymbolAddress((void**)&hhi, g_hhi);
        cudaGetSymbolAddress((void**)&hlo, g_hlo);
        cudaGetSymbolAddress((void**)&hp, g_h);
        cudaGetSymbolAddress((void**)&sp, g_s);
        cudaGetSymbolAddress((void**)&st, g_stats);
        cudaGetSymbolAddress((void**)&mw, g_mw1);
        cudaGetSymbolAddress((void**)&pp, g_part);
        cudaFuncSetAttribute(gemm_mma3_kernel, cudaFuncAttributeMaxDynamicSharedMemorySize, MM_SMEM);
    }

    const int OFF_LOGITS = 0;
    const int OFF_PROBS  = MROWS * NCLS;                 // 82944
    const int OFF_BBOX   = 2 * MROWS * NCLS;             // 165888
    const int OFF_MW     = OFF_BBOX + MROWS * NCLS * 4;  // 497664

    // 1) ROI align -> xhi/xlo [1024, 12544] (bf16 split)
    roi_align_kernel<<<MROWS, 256>>>(p2, p3, p4, p5, rois, xhi, xlo);

    // weight conversions (fp32 -> bf16 hi/lo)
    cvt_pair_kernel<<<(H1 * K1 + 255) / 256, 256>>>(conv1_w, w1hi, w1lo, H1 * K1);
    cvt_pair_kernel<<<(H1 * H1 + 255) / 256, 256>>>(conv2_w, w2hi, w2lo, H1 * H1);

    // 2) fc1 (tensor pipe, split-K=2): h = x @ conv1_w^T + b
    gemm_mma3_kernel<<<dim3(H1 / MM_BN, MROWS / MM_BM, 2), 256, MM_SMEM>>>(
        xhi, xlo, w1hi, w1lo, pp, H1, K1, K1 / 2);
    reduce_bias_kernel<<<(MROWS * H1 / 4 + 255) / 256, 256>>>(pp, conv1_b, hp, MROWS * H1, H1);

    // 3) BN1 + relu -> bf16 split
    bn_stats_kernel<<<H1, 256>>>(hp, st, MROWS, H1);
    bn_apply_relu_cvt_kernel<<<(MROWS * H1 + 255) / 256, 256>>>(hp, st, bn1_g, bn1_b, hhi, hlo, MROWS, H1);

    // 4) fc2 (tensor pipe, split-K=2): s = h @ conv2_w^T + b
    gemm_mma3_kernel<<<dim3(H1 / MM_BN, MROWS / MM_BM, 2), 256, MM_SMEM>>>(
        hhi, hlo, w2hi, w2lo, pp, H1, H1, H1 / 2);
    reduce_bias_kernel<<<(MROWS * H1 / 4 + 255) / 256, 256>>>(pp, conv2_b, sp, MROWS * H1, H1);

    // 5) BN2 + relu (fp32)
    bn_stats_kernel<<<H1, 256>>>(sp, st, MROWS, H1);
    bn_apply_relu_kernel<<<(MROWS * H1 + 255) / 256, 256>>>(sp, st, bn2_g, bn2_b, MROWS, H1);

    // 6) heads (fp32)
    gemm_abt_kernel<<<dim3(2, 16), 256>>>(sp, cls_w, cls_b, out + OFF_LOGITS, MROWS, NCLS, H1, 0);
    gemm_abt_kernel<<<dim3(6, 16), 256>>>(sp, box_w, box_b, out + OFF_BBOX, MROWS, NCLS * 4, H1, 0);
    softmax_kernel<<<MROWS, 128>>>(out + OFF_LOGITS, out + OFF_PROBS);

    // 7) meta-weight MLP
    gemm_abt_kernel<<<dim3(16, 2), 256>>>(cls_w, tf1_w, tf1_b, mw, NCLS, H1, H1, 1);
    gemm_abt_kernel<<<dim3(4, 2), 256>>>(mw, tf2_w, tf2_b, out + OFF_MW, NCLS, 256, H1, 1);
}

// round 11
// speedup vs baseline: 1.4112x; 1.4112x over previous
#include <cuda_runtime.h>
#include <cuda_bf16.h>
#include <math.h>
#include <stdint.h>

#define BB 2
#define NN 512
#define CC 256
#define POOLP 7
#define NCLS 81
#define MROWS (BB*NN)          // 1024
#define K1 (CC*POOLP*POOLP)    // 12544
#define H1 1024
#define IMGSZ 1024.0f

// ---------------- scratch (device globals; no allocation allowed) ----------------
__device__ __nv_bfloat16 g_xhi[(size_t)MROWS * K1];
__device__ __nv_bfloat16 g_xlo[(size_t)MROWS * K1];
__device__ __nv_bfloat16 g_w1hi[(size_t)H1 * K1];
__device__ __nv_bfloat16 g_w1lo[(size_t)H1 * K1];
__device__ __nv_bfloat16 g_w2hi[(size_t)H1 * H1];
__device__ __nv_bfloat16 g_w2lo[(size_t)H1 * H1];
__device__ __nv_bfloat16 g_hhi[(size_t)MROWS * H1];
__device__ __nv_bfloat16 g_hlo[(size_t)MROWS * H1];
__device__ float g_h[MROWS * H1];           // fc1 pre-BN (fp32)
__device__ float g_s[MROWS * H1];           // fc2 pre/post BN ("shared")
__device__ float g_stats[2 * H1];           // mean, var per feature
__device__ float g_mw1[NCLS * H1];          // MLP intermediate

// ================= PTX helpers (base-target only: sm_80-class) =================
__device__ __forceinline__ uint32_t smem_u32(const void* p) {
    uint32_t a;
    asm("{ .reg .u64 t; cvta.to.shared.u64 t, %1; cvt.u32.u64 %0, t; }" : "=r"(a) : "l"(p));
    return a;
}
__device__ __forceinline__ void cp_async16(uint32_t dst, const void* src) {
    asm volatile("cp.async.cg.shared.global [%0], [%1], 16;" :: "r"(dst), "l"(src) : "memory");
}
__device__ __forceinline__ void ldsm_x4(uint32_t* r, uint32_t addr) {
    asm volatile("ldmatrix.sync.aligned.m8n8.x4.shared.b16 {%0,%1,%2,%3}, [%4];"
                 : "=r"(r[0]), "=r"(r[1]), "=r"(r[2]), "=r"(r[3]) : "r"(addr));
}
__device__ __forceinline__ void mma16816(float* d, const uint32_t* a, const uint32_t* b) {
    asm volatile("mma.sync.aligned.m16n8k16.row.col.f32.bf16.bf16.f32 "
                 "{%0,%1,%2,%3}, {%4,%5,%6,%7}, {%8,%9}, {%0,%1,%2,%3};"
                 : "+f"(d[0]), "+f"(d[1]), "+f"(d[2]), "+f"(d[3])
                 : "r"(a[0]), "r"(a[1]), "r"(a[2]), "r"(a[3]), "r"(b[0]), "r"(b[1]));
}

// ================= mma.sync 3x-bf16 GEMM: C[M,N] = A[M,K] @ B[N,K]^T + bias ====
// Requires M % 64 == 0, N % 128 == 0, K % 32 == 0.
// 3-stage cp.async pipeline, one __syncthreads per K-chunk.
#define MM_BM 64
#define MM_BN 128
#define MM_BK 32
#define MM_RSTRIDE 80                   // bytes per smem row (32 bf16 + 16B pad)
#define MM_ABYTES (MM_BM * MM_RSTRIDE)  // 5120
#define MM_BBYTES (MM_BN * MM_RSTRIDE)  // 10240
#define MM_BUF (2*MM_ABYTES + 2*MM_BBYTES)  // 30720 per stage
#define MM_STAGES 3
#define MM_SMEM (MM_STAGES*MM_BUF)          // 92160

__global__ void __launch_bounds__(256, 1)
gemm_mma3_kernel(const __nv_bfloat16* __restrict__ Ahi, const __nv_bfloat16* __restrict__ Alo,
                 const __nv_bfloat16* __restrict__ Bhi, const __nv_bfloat16* __restrict__ Blo,
                 const float* __restrict__ bias, float* __restrict__ C, int N, int K)
{
    extern __shared__ char smem[];
    uint32_t sb = smem_u32(smem);
    int tid = threadIdx.x;
    int wid = tid >> 5, lane = tid & 31;
    int rowBase = blockIdx.y * MM_BM;
    int colBase = blockIdx.x * MM_BN;
    int warp_m = wid >> 2;      // 0..1  -> 32 rows each (2 m-tiles of 16)
    int warp_n = wid & 3;       // 0..3  -> 32 cols each (4 n-tiles of 8)
    int m_base = warp_m * 32;
    int n_base = warp_n * 32;

    float acc[2][4][4];
    #pragma unroll
    for (int mt = 0; mt < 2; mt++)
        #pragma unroll
        for (int nt = 0; nt < 4; nt++)
            #pragma unroll
            for (int j = 0; j < 4; j++) acc[mt][nt][j] = 0.f;

    int nc = K / MM_BK;

    // per-thread load indices (hoisted)
    int la_t = tid >> 8;                 // always 0 for first A pass
    (void)la_t;

    auto load_chunk = [&](int c, int slot) {
        uint32_t base = sb + (uint32_t)slot * MM_BUF;
        int k0 = c * MM_BK;
        #pragma unroll
        for (int i = 0; i < 2; i++) {                 // A: 512 x 16B segments (hi+lo)
            int id = tid + i * 256;
            int t = id >> 8;                          // 0=hi 1=lo
            int s = id & 255;
            int r = s >> 2, cseg = s & 3;
            const __nv_bfloat16* src = (t ? Alo : Ahi) + (size_t)(rowBase + r) * K + k0 + cseg * 8;
            cp_async16(base + (uint32_t)t * MM_ABYTES + (uint32_t)(r * MM_RSTRIDE + cseg * 16), src);
        }
        #pragma unroll
        for (int i = 0; i < 4; i++) {                 // B: 1024 x 16B segments (hi+lo)
            int id = tid + i * 256;
            int t = id >> 9;
            int s = id & 511;
            int r = s >> 2, cseg = s & 3;
            const __nv_bfloat16* src = (t ? Blo : Bhi) + (size_t)(colBase + r) * K + k0 + cseg * 8;
            cp_async16(base + 2 * MM_ABYTES + (uint32_t)t * MM_BBYTES + (uint32_t)(r * MM_RSTRIDE + cseg * 16), src);
        }
        asm volatile("cp.async.commit_group;" ::: "memory");
    };

    // prologue: 2-deep prefetch
    load_chunk(0, 0);
    load_chunk(1, 1);

    // hoisted fragment address components
    int arow = m_base + (lane & 15);
    uint32_t acol_base = (uint32_t)(((lane >> 4) << 3) * 2);
    int brow = n_base + ((lane >= 16) ? 8 : 0) + (lane & 7);
    uint32_t bcol_base = (uint32_t)((((lane >> 3) & 1) << 3) * 2);

    for (int c = 0; c < nc; c++) {
        if (c + 1 < nc) {
            asm volatile("cp.async.wait_group 1;" ::: "memory");
        } else {
            asm volatile("cp.async.wait_group 0;" ::: "memory");
        }
        __syncthreads();   // chunk c visible to all; all warps done with slot (c+2)%3's old data

        if (c + 2 < nc) load_chunk(c + 2, (c + 2) % MM_STAGES);

        uint32_t abase = sb + (uint32_t)(c % MM_STAGES) * MM_BUF;
        uint32_t bbase = abase + 2 * MM_ABYTES;

        #pragma unroll
        for (int ks = 0; ks < 2; ks++) {
            uint32_t ahi[2][4], alo[2][4];
            {
                uint32_t acol = acol_base + (uint32_t)(ks * 32);
                #pragma unroll
                for (int mt = 0; mt < 2; mt++) {
                    uint32_t addr = abase + (uint32_t)((arow + mt * 16) * MM_RSTRIDE) + acol;
                    ldsm_x4(ahi[mt], addr);
                    ldsm_x4(alo[mt], addr + MM_ABYTES);
                }
            }
            uint32_t bh[4][2], bl[4][2];
            {
                uint32_t bcol = bcol_base + (uint32_t)(ks * 32);
                #pragma unroll
                for (int np = 0; np < 2; np++) {
                    uint32_t addr = bbase + (uint32_t)((brow + np * 16) * MM_RSTRIDE) + bcol;
                    uint32_t r4[4];
                    ldsm_x4(r4, addr);
                    bh[np*2][0] = r4[0]; bh[np*2][1] = r4[1];
                    bh[np*2+1][0] = r4[2]; bh[np*2+1][1] = r4[3];
                    ldsm_x4(r4, addr + MM_BBYTES);
                    bl[np*2][0] = r4[0]; bl[np*2][1] = r4[1];
                    bl[np*2+1][0] = r4[2]; bl[np*2+1][1] = r4[3];
                }
            }
            #pragma unroll
            for (int mt = 0; mt < 2; mt++)
                #pragma unroll
                for (int nt = 0; nt < 4; nt++) {
                    mma16816(acc[mt][nt], ahi[mt], bh[nt]);
                    mma16816(acc[mt][nt], ahi[mt], bl[nt]);
                    mma16816(acc[mt][nt], alo[mt], bh[nt]);
                }
        }
        // no trailing sync: next iteration's sync protects slot reuse
    }

    // ---- epilogue: bias + store ----
    int g = lane >> 2, t2 = (lane & 3) * 2;
    #pragma unroll
    for (int mt = 0; mt < 2; mt++) {
        int row0 = rowBase + m_base + mt * 16 + g;
        #pragma unroll
        for (int nt = 0; nt < 4; nt++) {
            int col = colBase + n_base + nt * 8 + t2;
            float b0 = bias[col], b1 = bias[col + 1];
            float2* p0 = reinterpret_cast<float2*>(&C[(size_t)row0 * N + col]);
            float2* p1 = reinterpret_cast<float2*>(&C[(size_t)(row0 + 8) * N + col]);
            *p0 = make_float2(acc[mt][nt][0] + b0, acc[mt][nt][1] + b1);
            *p1 = make_float2(acc[mt][nt][2] + b0, acc[mt][nt][3] + b1);
        }
    }
}

// ---------------- ROI align -> bf16 hi/lo directly ----------------
__global__ void roi_align_kernel(const float* __restrict__ p2, const float* __restrict__ p3,
                                 const float* __restrict__ p4, const float* __restrict__ p5,
                                 const float* __restrict__ rois,
                                 __nv_bfloat16* __restrict__ Xhi, __nv_bfloat16* __restrict__ Xlo)
{
    int n = blockIdx.x;
    const float* roi = rois + (size_t)n * 4;
    float x1 = roi[0], y1 = roi[1], x2 = roi[2], y2 = roi[3];
    float area = (y2 - y1) * (x2 - x1);
    float lf = rintf(log2f(sqrtf(area) / 224.0f)) + 4.0f;   // half-to-even like jnp.round
    lf = fminf(fmaxf(lf, 2.0f), 5.0f);
    int lvl = (int)lf;

    const float* fm; int H;
    if (lvl == 2)      { fm = p2; H = 256; }
    else if (lvl == 3) { fm = p3; H = 128; }
    else if (lvl == 4) { fm = p4; H = 64;  }
    else               { fm = p5; H = 32;  }
    int W = H;

    float ny1 = y1 / IMGSZ, nx1 = x1 / IMGSZ, ny2 = y2 / IMGSZ, nx2 = x2 / IMGSZ;

    __shared__ int   s_y0[POOLP], s_y1[POOLP], s_x0[POOLP], s_x1[POOLP];
    __shared__ float s_ly[POOLP], s_lx[POOLP];

    int t = threadIdx.x;
    if (t < POOLP) {
        float g = (float)t / (float)(POOLP - 1);
        float ys = (ny1 + g * (ny2 - ny1)) * (float)(H - 1);
        float y0f = floorf(ys);
        s_ly[t] = ys - y0f;
        s_y0[t] = (int)fminf(fmaxf(y0f, 0.0f), (float)(H - 1));
        s_y1[t] = (int)fminf(fmaxf(y0f + 1.0f, 0.0f), (float)(H - 1));
    } else if (t < 2 * POOLP) {
        int j = t - POOLP;
        float g = (float)j / (float)(POOLP - 1);
        float xs = (nx1 + g * (nx2 - nx1)) * (float)(W - 1);
        float x0f = floorf(xs);
        s_lx[j] = xs - x0f;
        s_x0[j] = (int)fminf(fmaxf(x0f, 0.0f), (float)(W - 1));
        s_x1[j] = (int)fminf(fmaxf(x0f + 1.0f, 0.0f), (float)(W - 1));
    }
    __syncthreads();

    int HW = H * W;
    for (int idx = threadIdx.x; idx < K1; idx += blockDim.x) {
        int c  = idx / (POOLP * POOLP);
        int p  = idx % (POOLP * POOLP);
        int py = p / POOLP, px = p % POOLP;
        const float* plane = fm + (size_t)c * HW;
        float ly = s_ly[py], lx = s_lx[px];
        int y0 = s_y0[py], y1i = s_y1[py], x0 = s_x0[px], x1i = s_x1[px];
        float v00 = plane[y0  * W + x0 ];
        float v01 = plane[y0  * W + x1i];
        float v10 = plane[y1i * W + x0 ];
        float v11 = plane[y1i * W + x1i];
        float val = v00 * (1.0f - ly) * (1.0f - lx)
                  + v01 * (1.0f - ly) * lx
                  + v10 * ly * (1.0f - lx)
                  + v11 * ly * lx;
        __nv_bfloat16 h = __float2bfloat16(val);
        Xhi[(size_t)n * K1 + idx] = h;
        Xlo[(size_t)n * K1 + idx] = __float2bfloat16(val - __bfloat162float(h));
    }
}

// ---------------- fp32 -> (hi, lo) bf16 split ----------------
__global__ void cvt_pair_kernel(const float* __restrict__ src,
                                __nv_bfloat16* __restrict__ hi, __nv_bfloat16* __restrict__ lo, int n)
{
    int i = blockIdx.x * blockDim.x + threadIdx.x;
    if (i < n) {
        float v = src[i];
        __nv_bfloat16 h = __float2bfloat16(v);
        hi[i] = h;
        lo[i] = __float2bfloat16(v - __bfloat162float(h));
    }
}

// ---------------- fp32 tiled GEMM for small heads: C = A @ B^T + bias ----------------
#define BM 64
#define BN 64
#define BK 16
__global__ void gemm_abt_kernel(const float* __restrict__ A, const float* __restrict__ B,
                                const float* __restrict__ bias, float* __restrict__ C,
                                int M, int N, int K, int act)
{
    __shared__ float As[BK][BM];
    __shared__ float Bs[BK][BN];

    int tid = threadIdx.x;
    int tx = tid & 15;
    int ty = tid >> 4;
    int rowBase = blockIdx.y * BM;
    int colBase = blockIdx.x * BN;
    int lr = tid >> 2;
    int lk = (tid & 3) * 4;

    float acc[4][4] = {{0.f}};

    for (int k0 = 0; k0 < K; k0 += BK) {
        float4 av = make_float4(0.f, 0.f, 0.f, 0.f);
        int ar = rowBase + lr;
        if (ar < M) av = *reinterpret_cast<const float4*>(&A[(size_t)ar * K + k0 + lk]);
        As[lk + 0][lr] = av.x; As[lk + 1][lr] = av.y;
        As[lk + 2][lr] = av.z; As[lk + 3][lr] = av.w;

        float4 bv = make_float4(0.f, 0.f, 0.f, 0.f);
        int br = colBase + lr;
        if (br < N) bv = *reinterpret_cast<const float4*>(&B[(size_t)br * K + k0 + lk]);
        Bs[lk + 0][lr] = bv.x; Bs[lk + 1][lr] = bv.y;
        Bs[lk + 2][lr] = bv.z; Bs[lk + 3][lr] = bv.w;

        __syncthreads();

        #pragma unroll
        for (int k = 0; k < BK; k++) {
            float4 a = *reinterpret_cast<const float4*>(&As[k][ty * 4]);
            float4 b = *reinterpret_cast<const float4*>(&Bs[k][tx * 4]);
            float aa[4] = {a.x, a.y, a.z, a.w};
            float bb[4] = {b.x, b.y, b.z, b.w};
            #pragma unroll
            for (int i = 0; i < 4; i++)
                #pragma unroll
                for (int j = 0; j < 4; j++)
                    acc[i][j] = fmaf(aa[i], bb[j], acc[i][j]);
        }
        __syncthreads();
    }

    #pragma unroll
    for (int i = 0; i < 4; i++) {
        int row = rowBase + ty * 4 + i;
        if (row >= M) continue;
        #pragma unroll
        for (int j = 0; j < 4; j++) {
            int col = colBase + tx * 4 + j;
            if (col >= N) continue;
            float v = acc[i][j] + bias[col];
            if (act == 1) v = (v >= 0.f) ? v : 0.01f * v;
            C[(size_t)row * N + col] = v;
        }
    }
}

// ---------------- batch-norm stats ----------------
__global__ void bn_stats_kernel(const float* __restrict__ Hm, float* __restrict__ stats,
                                int M, int N)
{
    int col = blockIdx.x;
    int tid = threadIdx.x;
    float s = 0.f, s2 = 0.f;
    for (int r = tid; r < M; r += blockDim.x) {
        float v = Hm[(size_t)r * N + col];
        s += v; s2 += v * v;
    }
    __shared__ float sh[256], sh2[256];
    sh[tid] = s; sh2[tid] = s2;
    __syncthreads();
    for (int o = 128; o > 0; o >>= 1) {
        if (tid < o) { sh[tid] += sh[tid + o]; sh2[tid] += sh2[tid + o]; }
        __syncthreads();
    }
    if (tid == 0) {
        float m = sh[0] / (float)M;
        stats[col]     = m;
        stats[N + col] = sh2[0] / (float)M - m * m;
    }
}

// BN1: apply + relu, write bf16 hi/lo (feeds tensor GEMM2)
__global__ void bn_apply_relu_cvt_kernel(const float* __restrict__ Hm, const float* __restrict__ stats,
                                         const float* __restrict__ gam, const float* __restrict__ bet,
                                         __nv_bfloat16* __restrict__ hi, __nv_bfloat16* __restrict__ lo,
                                         int M, int N)
{
    int idx = blockIdx.x * blockDim.x + threadIdx.x;
    if (idx >= M * N) return;
    int col = idx % N;
    float m = stats[col], v = stats[N + col];
    float h = (Hm[idx] - m) * rsqrtf(v + 0.001f) * gam[col] + bet[col];
    h = fmaxf(h, 0.f);
    __nv_bfloat16 hh = __float2bfloat16(h);
    hi[idx] = hh;
    lo[idx] = __float2bfloat16(h - __bfloat162float(hh));
}

// BN2: apply + relu in-place fp32 (feeds fp32 heads)
__global__ void bn_apply_relu_kernel(float* __restrict__ Hm, const float* __restrict__ stats,
                                     const float* __restrict__ gam, const float* __restrict__ bet,
                                     int M, int N)
{
    int idx = blockIdx.x * blockDim.x + threadIdx.x;
    if (idx >= M * N) return;
    int col = idx % N;
    float m = stats[col], v = stats[N + col];
    float h = (Hm[idx] - m) * rsqrtf(v + 0.001f) * gam[col] + bet[col];
    Hm[idx] = fmaxf(h, 0.f);
}

// ---------------- softmax over 81 classes per row ----------------
__global__ void softmax_kernel(const float* __restrict__ logits, float* __restrict__ probs)
{
    int row = blockIdx.x;
    int t = threadIdx.x;   // 128 threads
    __shared__ float red[128];
    float v = (t < NCLS) ? logits[(size_t)row * NCLS + t] : -INFINITY;
    red[t] = v;
    __syncthreads();
    for (int o = 64; o > 0; o >>= 1) {
        if (t < o) red[t] = fmaxf(red[t], red[t + o]);
        __syncthreads();
    }
    float mx = red[0];
    __syncthreads();
    float e = (t < NCLS) ? expf(v - mx) : 0.f;
    red[t] = e;
    __syncthreads();
    for (int o = 64; o > 0; o >>= 1) {
        if (t < o) red[t] += red[t + o];
        __syncthreads();
    }
    if (t < NCLS) probs[(size_t)row * NCLS + t] = e / red[0];
}

// ---------------- launch ----------------
extern "C" void kernel_launch(void* const* d_in, const int* in_sizes, int n_in,
                              void* d_out, int out_size)
{
    const float* p2      = (const float*)d_in[0];
    const float* p3      = (const float*)d_in[1];
    const float* p4      = (const float*)d_in[2];
    const float* p5      = (const float*)d_in[3];
    const float* rois    = (const float*)d_in[4];
    const float* conv1_w = (const float*)d_in[5];
    const float* conv1_b = (const float*)d_in[6];
    const float* bn1_g   = (const float*)d_in[7];
    const float* bn1_b   = (const float*)d_in[8];
    const float* conv2_w = (const float*)d_in[9];
    const float* conv2_b = (const float*)d_in[10];
    const float* bn2_g   = (const float*)d_in[11];
    const float* bn2_b   = (const float*)d_in[12];
    const float* cls_w   = (const float*)d_in[13];
    const float* cls_b   = (const float*)d_in[14];
    const float* box_w   = (const float*)d_in[15];
    const float* box_b   = (const float*)d_in[16];
    const float* tf1_w   = (const float*)d_in[17];
    const float* tf1_b   = (const float*)d_in[18];
    const float* tf2_w   = (const float*)d_in[19];
    const float* tf2_b   = (const float*)d_in[20];
    float* out = (float*)d_out;

    static __nv_bfloat16 *xhi=nullptr,*xlo=nullptr,*w1hi=nullptr,*w1lo=nullptr,*w2hi=nullptr,*w2lo=nullptr,*hhi=nullptr,*hlo=nullptr;
    static float *hp=nullptr, *sp=nullptr, *st=nullptr, *mw=nullptr;
    if (!hp) {
        cudaGetSymbolAddress((void**)&xhi, g_xhi);
        cudaGetSymbolAddress((void**)&xlo, g_xlo);
        cudaGetSymbolAddress((void**)&w1hi, g_w1hi);
        cudaGetSymbolAddress((void**)&w1lo, g_w1lo);
        cudaGetSymbolAddress((void**)&w2hi, g_w2hi);
        cudaGetSymbolAddress((void**)&w2lo, g_w2lo);
        cudaGetSymbolAddress((void**)&hhi, g_hhi);
        cudaGetSymbolAddress((void**)&hlo, g_hlo);
        cudaGetSymbolAddress((void**)&hp, g_h);
        cudaGetSymbolAddress((void**)&sp, g_s);
        cudaGetSymbolAddress((void**)&st, g_stats);
        cudaGetSymbolAddress((void**)&mw, g_mw1);
        cudaFuncSetAttribute(gemm_mma3_kernel, cudaFuncAttributeMaxDynamicSharedMemorySize, MM_SMEM);
    }

    const int OFF_LOGITS = 0;
    const int OFF_PROBS  = MROWS * NCLS;                 // 82944
    const int OFF_BBOX   = 2 * MROWS * NCLS;             // 165888
    const int OFF_MW     = OFF_BBOX + MROWS * NCLS * 4;  // 497664

    // 1) ROI align -> xhi/xlo [1024, 12544] (bf16 split)
    roi_align_kernel<<<MROWS, 256>>>(p2, p3, p4, p5, rois, xhi, xlo);

    // weight conversions (fp32 -> bf16 hi/lo)
    cvt_pair_kernel<<<(H1 * K1 + 255) / 256, 256>>>(conv1_w, w1hi, w1lo, H1 * K1);
    cvt_pair_kernel<<<(H1 * H1 + 255) / 256, 256>>>(conv2_w, w2hi, w2lo, H1 * H1);

    // 2) fc1 (tensor pipe, 3-stage pipeline): h = x @ conv1_w^T + b
    gemm_mma3_kernel<<<dim3(H1 / MM_BN, MROWS / MM_BM), 256, MM_SMEM>>>(
        xhi, xlo, w1hi, w1lo, conv1_b, hp, H1, K1);

    // 3) BN1 + relu -> bf16 split
    bn_stats_kernel<<<H1, 256>>>(hp, st, MROWS, H1);
    bn_apply_relu_cvt_kernel<<<(MROWS * H1 + 255) / 256, 256>>>(hp, st, bn1_g, bn1_b, hhi, hlo, MROWS, H1);

    // 4) fc2 (tensor pipe): s = h @ conv2_w^T + b
    gemm_mma3_kernel<<<dim3(H1 / MM_BN, MROWS / MM_BM), 256, MM_SMEM>>>(
        hhi, hlo, w2hi, w2lo, conv2_b, sp, H1, H1);

    // 5) BN2 + relu (fp32)
    bn_stats_kernel<<<H1, 256>>>(sp, st, MROWS, H1);
    bn_apply_relu_kernel<<<(MROWS * H1 + 255) / 256, 256>>>(sp, st, bn2_g, bn2_b, MROWS, H1);

    // 6) heads (fp32)
    gemm_abt_kernel<<<dim3(2, 16), 256>>>(sp, cls_w, cls_b, out + OFF_LOGITS, MROWS, NCLS, H1, 0);
    gemm_abt_kernel<<<dim3(6, 16), 256>>>(sp, box_w, box_b, out + OFF_BBOX, MROWS, NCLS * 4, H1, 0);
    softmax_kernel<<<MROWS, 128>>>(out + OFF_LOGITS, out + OFF_PROBS);

    // 7) meta-weight MLP
    gemm_abt_kernel<<<dim3(16, 2), 256>>>(cls_w, tf1_w, tf1_b, mw, NCLS, H1, H1, 1);
    gemm_abt_kernel<<<dim3(4, 2), 256>>>(mw, tf2_w, tf2_b, out + OFF_MW, NCLS, 256, H1, 1);
}

// round 12
// speedup vs baseline: 1.4148x; 1.0026x over previous
#include <cuda_runtime.h>
#include <cuda_bf16.h>
#include <math.h>
#include <stdint.h>

#define BB 2
#define NN 512
#define CC 256
#define POOLP 7
#define NCLS 81
#define MROWS (BB*NN)          // 1024
#define K1 (CC*POOLP*POOLP)    // 12544
#define H1 1024
#define IMGSZ 1024.0f

// ---------------- scratch (device globals; no allocation allowed) ----------------
__device__ __nv_bfloat16 g_xhi[(size_t)MROWS * K1];
__device__ __nv_bfloat16 g_xlo[(size_t)MROWS * K1];
__device__ __nv_bfloat16 g_w1hi[(size_t)H1 * K1];
__device__ __nv_bfloat16 g_w1lo[(size_t)H1 * K1];
__device__ __nv_bfloat16 g_w2hi[(size_t)H1 * H1];
__device__ __nv_bfloat16 g_w2lo[(size_t)H1 * H1];
__device__ __nv_bfloat16 g_hhi[(size_t)MROWS * H1];
__device__ __nv_bfloat16 g_hlo[(size_t)MROWS * H1];
__device__ float g_h[MROWS * H1];           // fc1 pre-BN (fp32)
__device__ float g_s[MROWS * H1];           // fc2 pre/post BN ("shared")
__device__ float g_stats[2 * H1];           // mean, var per feature
__device__ float g_mw1[NCLS * H1];          // MLP intermediate

// ================= PTX helpers (base-target only: sm_80-class) =================
__device__ __forceinline__ uint32_t smem_u32(const void* p) {
    uint32_t a;
    asm("{ .reg .u64 t; cvta.to.shared.u64 t, %1; cvt.u32.u64 %0, t; }" : "=r"(a) : "l"(p));
    return a;
}
__device__ __forceinline__ void cp_async16(uint32_t dst, const void* src) {
    asm volatile("cp.async.cg.shared.global [%0], [%1], 16;" :: "r"(dst), "l"(src) : "memory");
}
__device__ __forceinline__ void ldsm_x4(uint32_t* r, uint32_t addr) {
    asm volatile("ldmatrix.sync.aligned.m8n8.x4.shared.b16 {%0,%1,%2,%3}, [%4];"
                 : "=r"(r[0]), "=r"(r[1]), "=r"(r[2]), "=r"(r[3]) : "r"(addr));
}
__device__ __forceinline__ void mma16816(float* d, const uint32_t* a, const uint32_t* b) {
    asm volatile("mma.sync.aligned.m16n8k16.row.col.f32.bf16.bf16.f32 "
                 "{%0,%1,%2,%3}, {%4,%5,%6,%7}, {%8,%9}, {%0,%1,%2,%3};"
                 : "+f"(d[0]), "+f"(d[1]), "+f"(d[2]), "+f"(d[3])
                 : "r"(a[0]), "r"(a[1]), "r"(a[2]), "r"(a[3]), "r"(b[0]), "r"(b[1]));
}

// ================= mma.sync 3x-bf16 GEMM: C[M,N] = A[M,K] @ B[N,K]^T + bias ====
// Requires M % 64 == 0, N % 128 == 0, K % 32 == 0.
// 3-stage cp.async pipeline; whole-chunk fragment preload; pass-ordered MMAs.
#define MM_BM 64
#define MM_BN 128
#define MM_BK 32
#define MM_RSTRIDE 80                   // bytes per smem row (32 bf16 + 16B pad)
#define MM_ABYTES (MM_BM * MM_RSTRIDE)  // 5120
#define MM_BBYTES (MM_BN * MM_RSTRIDE)  // 10240
#define MM_BUF (2*MM_ABYTES + 2*MM_BBYTES)  // 30720 per stage
#define MM_STAGES 3
#define MM_SMEM (MM_STAGES*MM_BUF)          // 92160

__global__ void __launch_bounds__(256, 1)
gemm_mma3_kernel(const __nv_bfloat16* __restrict__ Ahi, const __nv_bfloat16* __restrict__ Alo,
                 const __nv_bfloat16* __restrict__ Bhi, const __nv_bfloat16* __restrict__ Blo,
                 const float* __restrict__ bias, float* __restrict__ C, int N, int K)
{
    extern __shared__ char smem[];
    uint32_t sb = smem_u32(smem);
    int tid = threadIdx.x;
    int wid = tid >> 5, lane = tid & 31;
    int rowBase = blockIdx.y * MM_BM;
    int colBase = blockIdx.x * MM_BN;
    int warp_m = wid >> 2;      // 0..1  -> 32 rows each (2 m-tiles of 16)
    int warp_n = wid & 3;       // 0..3  -> 32 cols each (4 n-tiles of 8)
    int m_base = warp_m * 32;
    int n_base = warp_n * 32;

    float acc[2][4][4];
    #pragma unroll
    for (int mt = 0; mt < 2; mt++)
        #pragma unroll
        for (int nt = 0; nt < 4; nt++)
            #pragma unroll
            for (int j = 0; j < 4; j++) acc[mt][nt][j] = 0.f;

    int nc = K / MM_BK;

    auto load_chunk = [&](int c, int slot) {
        uint32_t base = sb + (uint32_t)slot * MM_BUF;
        int k0 = c * MM_BK;
        #pragma unroll
        for (int i = 0; i < 2; i++) {                 // A: 512 x 16B segments (hi+lo)
            int id = tid + i * 256;
            int t = id >> 8;                          // 0=hi 1=lo
            int s = id & 255;
            int r = s >> 2, cseg = s & 3;
            const __nv_bfloat16* src = (t ? Alo : Ahi) + (size_t)(rowBase + r) * K + k0 + cseg * 8;
            cp_async16(base + (uint32_t)t * MM_ABYTES + (uint32_t)(r * MM_RSTRIDE + cseg * 16), src);
        }
        #pragma unroll
        for (int i = 0; i < 4; i++) {                 // B: 1024 x 16B segments (hi+lo)
            int id = tid + i * 256;
            int t = id >> 9;
            int s = id & 511;
            int r = s >> 2, cseg = s & 3;
            const __nv_bfloat16* src = (t ? Blo : Bhi) + (size_t)(colBase + r) * K + k0 + cseg * 8;
            cp_async16(base + 2 * MM_ABYTES + (uint32_t)t * MM_BBYTES + (uint32_t)(r * MM_RSTRIDE + cseg * 16), src);
        }
        asm volatile("cp.async.commit_group;" ::: "memory");
    };

    // prologue: 2-deep prefetch
    load_chunk(0, 0);
    load_chunk(1, 1);

    // hoisted fragment address components
    int arow = m_base + (lane & 15);
    uint32_t acol_base = (uint32_t)(((lane >> 4) << 3) * 2);
    int brow = n_base + ((lane >= 16) ? 8 : 0) + (lane & 7);
    uint32_t bcol_base = (uint32_t)((((lane >> 3) & 1) << 3) * 2);

    for (int c = 0; c < nc; c++) {
        if (c + 1 < nc) {
            asm volatile("cp.async.wait_group 1;" ::: "memory");
        } else {
            asm volatile("cp.async.wait_group 0;" ::: "memory");
        }
        __syncthreads();   // chunk c visible; all warps done with slot (c+2)%3's old data

        if (c + 2 < nc) load_chunk(c + 2, (c + 2) % MM_STAGES);

        uint32_t abase = sb + (uint32_t)(c % MM_STAGES) * MM_BUF;
        uint32_t bbase = abase + 2 * MM_ABYTES;

        // ---- preload ALL fragments for this chunk (both k16 halves) ----
        uint32_t ahi[2][2][4], alo[2][2][4];   // [ks][mt][4]
        uint32_t bh[2][4][2],  bl[2][4][2];    // [ks][nt][2]
        #pragma unroll
        for (int ks = 0; ks < 2; ks++) {
            uint32_t acol = acol_base + (uint32_t)(ks * 32);
            #pragma unroll
            for (int mt = 0; mt < 2; mt++) {
                uint32_t addr = abase + (uint32_t)((arow + mt * 16) * MM_RSTRIDE) + acol;
                ldsm_x4(ahi[ks][mt], addr);
                ldsm_x4(alo[ks][mt], addr + MM_ABYTES);
            }
            uint32_t bcol = bcol_base + (uint32_t)(ks * 32);
            #pragma unroll
            for (int np = 0; np < 2; np++) {
                uint32_t addr = bbase + (uint32_t)((brow + np * 16) * MM_RSTRIDE) + bcol;
                uint32_t r4[4];
                ldsm_x4(r4, addr);
                bh[ks][np*2][0] = r4[0]; bh[ks][np*2][1] = r4[1];
                bh[ks][np*2+1][0] = r4[2]; bh[ks][np*2+1][1] = r4[3];
                ldsm_x4(r4, addr + MM_BBYTES);
                bl[ks][np*2][0] = r4[0]; bl[ks][np*2][1] = r4[1];
                bl[ks][np*2+1][0] = r4[2]; bl[ks][np*2+1][1] = r4[3];
            }
        }

        // ---- pass-ordered MMAs: 8 independent ops per pass, RAW >= 8 apart ----
        #pragma unroll
        for (int ks = 0; ks < 2; ks++) {
            #pragma unroll
            for (int mt = 0; mt < 2; mt++)
                #pragma unroll
                for (int nt = 0; nt < 4; nt++)
                    mma16816(acc[mt][nt], ahi[ks][mt], bh[ks][nt]);
            #pragma unroll
            for (int mt = 0; mt < 2; mt++)
                #pragma unroll
                for (int nt = 0; nt < 4; nt++)
                    mma16816(acc[mt][nt], ahi[ks][mt], bl[ks][nt]);
            #pragma unroll
            for (int mt = 0; mt < 2; mt++)
                #pragma unroll
                for (int nt = 0; nt < 4; nt++)
                    mma16816(acc[mt][nt], alo[ks][mt], bh[ks][nt]);
        }
        // no trailing sync: next iteration's sync protects slot reuse
    }

    // ---- epilogue: bias + store ----
    int g = lane >> 2, t2 = (lane & 3) * 2;
    #pragma unroll
    for (int mt = 0; mt < 2; mt++) {
        int row0 = rowBase + m_base + mt * 16 + g;
        #pragma unroll
        for (int nt = 0; nt < 4; nt++) {
            int col = colBase + n_base + nt * 8 + t2;
            float b0 = bias[col], b1 = bias[col + 1];
            float2* p0 = reinterpret_cast<float2*>(&C[(size_t)row0 * N + col]);
            float2* p1 = reinterpret_cast<float2*>(&C[(size_t)(row0 + 8) * N + col]);
            *p0 = make_float2(acc[mt][nt][0] + b0, acc[mt][nt][1] + b1);
            *p1 = make_float2(acc[mt][nt][2] + b0, acc[mt][nt][3] + b1);
        }
    }
}

// ---------------- ROI align -> bf16 hi/lo directly ----------------
__global__ void roi_align_kernel(const float* __restrict__ p2, const float* __restrict__ p3,
                                 const float* __restrict__ p4, const float* __restrict__ p5,
                                 const float* __restrict__ rois,
                                 __nv_bfloat16* __restrict__ Xhi, __nv_bfloat16* __restrict__ Xlo)
{
    int n = blockIdx.x;
    const float* roi = rois + (size_t)n * 4;
    float x1 = roi[0], y1 = roi[1], x2 = roi[2], y2 = roi[3];
    float area = (y2 - y1) * (x2 - x1);
    float lf = rintf(log2f(sqrtf(area) / 224.0f)) + 4.0f;   // half-to-even like jnp.round
    lf = fminf(fmaxf(lf, 2.0f), 5.0f);
    int lvl = (int)lf;

    const float* fm; int H;
    if (lvl == 2)      { fm = p2; H = 256; }
    else if (lvl == 3) { fm = p3; H = 128; }
    else if (lvl == 4) { fm = p4; H = 64;  }
    else               { fm = p5; H = 32;  }
    int W = H;

    float ny1 = y1 / IMGSZ, nx1 = x1 / IMGSZ, ny2 = y2 / IMGSZ, nx2 = x2 / IMGSZ;

    __shared__ int   s_y0[POOLP], s_y1[POOLP], s_x0[POOLP], s_x1[POOLP];
    __shared__ float s_ly[POOLP], s_lx[POOLP];

    int t = threadIdx.x;
    if (t < POOLP) {
        float g = (float)t / (float)(POOLP - 1);
        float ys = (ny1 + g * (ny2 - ny1)) * (float)(H - 1);
        float y0f = floorf(ys);
        s_ly[t] = ys - y0f;
        s_y0[t] = (int)fminf(fmaxf(y0f, 0.0f), (float)(H - 1));
        s_y1[t] = (int)fminf(fmaxf(y0f + 1.0f, 0.0f), (float)(H - 1));
    } else if (t < 2 * POOLP) {
        int j = t - POOLP;
        float g = (float)j / (float)(POOLP - 1);
        float xs = (nx1 + g * (nx2 - nx1)) * (float)(W - 1);
        float x0f = floorf(xs);
        s_lx[j] = xs - x0f;
        s_x0[j] = (int)fminf(fmaxf(x0f, 0.0f), (float)(W - 1));
        s_x1[j] = (int)fminf(fmaxf(x0f + 1.0f, 0.0f), (float)(W - 1));
    }
    __syncthreads();

    int HW = H * W;
    for (int idx = threadIdx.x; idx < K1; idx += blockDim.x) {
        int c  = idx / (POOLP * POOLP);
        int p  = idx % (POOLP * POOLP);
        int py = p / POOLP, px = p % POOLP;
        const float* plane = fm + (size_t)c * HW;
        float ly = s_ly[py], lx = s_lx[px];
        int y0 = s_y0[py], y1i = s_y1[py], x0 = s_x0[px], x1i = s_x1[px];
        float v00 = plane[y0  * W + x0 ];
        float v01 = plane[y0  * W + x1i];
        float v10 = plane[y1i * W + x0 ];
        float v11 = plane[y1i * W + x1i];
        float val = v00 * (1.0f - ly) * (1.0f - lx)
                  + v01 * (1.0f - ly) * lx
                  + v10 * ly * (1.0f - lx)
                  + v11 * ly * lx;
        __nv_bfloat16 h = __float2bfloat16(val);
        Xhi[(size_t)n * K1 + idx] = h;
        Xlo[(size_t)n * K1 + idx] = __float2bfloat16(val - __bfloat162float(h));
    }
}

// ---------------- fp32 -> (hi, lo) bf16 split ----------------
__global__ void cvt_pair_kernel(const float* __restrict__ src,
                                __nv_bfloat16* __restrict__ hi, __nv_bfloat16* __restrict__ lo, int n)
{
    int i = blockIdx.x * blockDim.x + threadIdx.x;
    if (i < n) {
        float v = src[i];
        __nv_bfloat16 h = __float2bfloat16(v);
        hi[i] = h;
        lo[i] = __float2bfloat16(v - __bfloat162float(h));
    }
}

// ---------------- fp32 tiled GEMM for small heads: C = A @ B^T + bias ----------------
#define BM 64
#define BN 64
#define BK 16
__global__ void gemm_abt_kernel(const float* __restrict__ A, const float* __restrict__ B,
                                const float* __restrict__ bias, float* __restrict__ C,
                                int M, int N, int K, int act)
{
    __shared__ float As[BK][BM];
    __shared__ float Bs[BK][BN];

    int tid = threadIdx.x;
    int tx = tid & 15;
    int ty = tid >> 4;
    int rowBase = blockIdx.y * BM;
    int colBase = blockIdx.x * BN;
    int lr = tid >> 2;
    int lk = (tid & 3) * 4;

    float acc[4][4] = {{0.f}};

    for (int k0 = 0; k0 < K; k0 += BK) {
        float4 av = make_float4(0.f, 0.f, 0.f, 0.f);
        int ar = rowBase + lr;
        if (ar < M) av = *reinterpret_cast<const float4*>(&A[(size_t)ar * K + k0 + lk]);
        As[lk + 0][lr] = av.x; As[lk + 1][lr] = av.y;
        As[lk + 2][lr] = av.z; As[lk + 3][lr] = av.w;

        float4 bv = make_float4(0.f, 0.f, 0.f, 0.f);
        int br = colBase + lr;
        if (br < N) bv = *reinterpret_cast<const float4*>(&B[(size_t)br * K + k0 + lk]);
        Bs[lk + 0][lr] = bv.x; Bs[lk + 1][lr] = bv.y;
        Bs[lk + 2][lr] = bv.z; Bs[lk + 3][lr] = bv.w;

        __syncthreads();

        #pragma unroll
        for (int k = 0; k < BK; k++) {
            float4 a = *reinterpret_cast<const float4*>(&As[k][ty * 4]);
            float4 b = *reinterpret_cast<const float4*>(&Bs[k][tx * 4]);
            float aa[4] = {a.x, a.y, a.z, a.w};
            float bb[4] = {b.x, b.y, b.z, b.w};
            #pragma unroll
            for (int i = 0; i < 4; i++)
                #pragma unroll
                for (int j = 0; j < 4; j++)
                    acc[i][j] = fmaf(aa[i], bb[j], acc[i][j]);
        }
        __syncthreads();
    }

    #pragma unroll
    for (int i = 0; i < 4; i++) {
        int row = rowBase + ty * 4 + i;
        if (row >= M) continue;
        #pragma unroll
        for (int j = 0; j < 4; j++) {
            int col = colBase + tx * 4 + j;
            if (col >= N) continue;
            float v = acc[i][j] + bias[col];
            if (act == 1) v = (v >= 0.f) ? v : 0.01f * v;
            C[(size_t)row * N + col] = v;
        }
    }
}

// ---------------- batch-norm stats (coalesced: 32 cols x 8 rows per block) ----------------
__global__ void bn_stats_kernel(const float* __restrict__ Hm, float* __restrict__ stats,
                                int M, int N)
{
    int x = threadIdx.x & 31, y = threadIdx.x >> 5;   // 256 threads
    int col = blockIdx.x * 32 + x;
    float s = 0.f, s2 = 0.f;
    for (int r = y; r < M; r += 8) {
        float v = Hm[(size_t)r * N + col];
        s += v; s2 += v * v;
    }
    __shared__ float sh[8][32], sh2[8][32];
    sh[y][x] = s; sh2[y][x] = s2;
    __syncthreads();
    if (y == 0) {
        #pragma unroll
        for (int i = 1; i < 8; i++) { s += sh[i][x]; s2 += sh2[i][x]; }
        float m = s / (float)M;
        stats[col]     = m;
        stats[N + col] = s2 / (float)M - m * m;
    }
}

// BN1: apply + relu, write bf16 hi/lo (feeds tensor GEMM2)
__global__ void bn_apply_relu_cvt_kernel(const float* __restrict__ Hm, const float* __restrict__ stats,
                                         const float* __restrict__ gam, const float* __restrict__ bet,
                                         __nv_bfloat16* __restrict__ hi, __nv_bfloat16* __restrict__ lo,
                                         int M, int N)
{
    int idx = blockIdx.x * blockDim.x + threadIdx.x;
    if (idx >= M * N) return;
    int col = idx % N;
    float m = stats[col], v = stats[N + col];
    float h = (Hm[idx] - m) * rsqrtf(v + 0.001f) * gam[col] + bet[col];
    h = fmaxf(h, 0.f);
    __nv_bfloat16 hh = __float2bfloat16(h);
    hi[idx] = hh;
    lo[idx] = __float2bfloat16(h - __bfloat162float(hh));
}

// BN2: apply + relu in-place fp32 (feeds fp32 heads)
__global__ void bn_apply_relu_kernel(float* __restrict__ Hm, const float* __restrict__ stats,
                                     const float* __restrict__ gam, const float* __restrict__ bet,
                                     int M, int N)
{
    int idx = blockIdx.x * blockDim.x + threadIdx.x;
    if (idx >= M * N) return;
    int col = idx % N;
    float m = stats[col], v = stats[N + col];
    float h = (Hm[idx] - m) * rsqrtf(v + 0.001f) * gam[col] + bet[col];
    Hm[idx] = fmaxf(h, 0.f);
}

// ---------------- softmax over 81 classes per row ----------------
__global__ void softmax_kernel(const float* __restrict__ logits, float* __restrict__ probs)
{
    int row = blockIdx.x;
    int t = threadIdx.x;   // 128 threads
    __shared__ float red[128];
    float v = (t < NCLS) ? logits[(size_t)row * NCLS + t] : -INFINITY;
    red[t] = v;
    __syncthreads();
    for (int o = 64; o > 0; o >>= 1) {
        if (t < o) red[t] = fmaxf(red[t], red[t + o]);
        __syncthreads();
    }
    float mx = red[0];
    __syncthreads();
    float e = (t < NCLS) ? expf(v - mx) : 0.f;
    red[t] = e;
    __syncthreads();
    for (int o = 64; o > 0; o >>= 1) {
        if (t < o) red[t] += red[t + o];
        __syncthreads();
    }
    if (t < NCLS) probs[(size_t)row * NCLS + t] = e / red[0];
}

// ---------------- launch ----------------
extern "C" void kernel_launch(void* const* d_in, const int* in_sizes, int n_in,
                              void* d_out, int out_size)
{
    const float* p2      = (const float*)d_in[0];
    const float* p3      = (const float*)d_in[1];
    const float* p4      = (const float*)d_in[2];
    const float* p5      = (const float*)d_in[3];
    const float* rois    = (const float*)d_in[4];
    const float* conv1_w = (const float*)d_in[5];
    const float* conv1_b = (const float*)d_in[6];
    const float* bn1_g   = (const float*)d_in[7];
    const float* bn1_b   = (const float*)d_in[8];
    const float* conv2_w = (const float*)d_in[9];
    const float* conv2_b = (const float*)d_in[10];
    const float* bn2_g   = (const float*)d_in[11];
    const float* bn2_b   = (const float*)d_in[12];
    const float* cls_w   = (const float*)d_in[13];
    const float* cls_b   = (const float*)d_in[14];
    const float* box_w   = (const float*)d_in[15];
    const float* box_b   = (const float*)d_in[16];
    const float* tf1_w   = (const float*)d_in[17];
    const float* tf1_b   = (const float*)d_in[18];
    const float* tf2_w   = (const float*)d_in[19];
    const float* tf2_b   = (const float*)d_in[20];
    float* out = (float*)d_out;

    static __nv_bfloat16 *xhi=nullptr,*xlo=nullptr,*w1hi=nullptr,*w1lo=nullptr,*w2hi=nullptr,*w2lo=nullptr,*hhi=nullptr,*hlo=nullptr;
    static float *hp=nullptr, *sp=nullptr, *st=nullptr, *mw=nullptr;
    if (!hp) {
        cudaGetSymbolAddress((void**)&xhi, g_xhi);
        cudaGetSymbolAddress((void**)&xlo, g_xlo);
        cudaGetSymbolAddress((void**)&w1hi, g_w1hi);
        cudaGetSymbolAddress((void**)&w1lo, g_w1lo);
        cudaGetSymbolAddress((void**)&w2hi, g_w2hi);
        cudaGetSymbolAddress((void**)&w2lo, g_w2lo);
        cudaGetSymbolAddress((void**)&hhi, g_hhi);
        cudaGetSymbolAddress((void**)&hlo, g_hlo);
        cudaGetSymbolAddress((void**)&hp, g_h);
        cudaGetSymbolAddress((void**)&sp, g_s);
        cudaGetSymbolAddress((void**)&st, g_stats);
        cudaGetSymbolAddress((void**)&mw, g_mw1);
        cudaFuncSetAttribute(gemm_mma3_kernel, cudaFuncAttributeMaxDynamicSharedMemorySize, MM_SMEM);
    }

    const int OFF_LOGITS = 0;
    const int OFF_PROBS  = MROWS * NCLS;                 // 82944
    const int OFF_BBOX   = 2 * MROWS * NCLS;             // 165888
    const int OFF_MW     = OFF_BBOX + MROWS * NCLS * 4;  // 497664

    // 1) ROI align -> xhi/xlo [1024, 12544] (bf16 split)
    roi_align_kernel<<<MROWS, 256>>>(p2, p3, p4, p5, rois, xhi, xlo);

    // weight conversions (fp32 -> bf16 hi/lo)
    cvt_pair_kernel<<<(H1 * K1 + 255) / 256, 256>>>(conv1_w, w1hi, w1lo, H1 * K1);
    cvt_pair_kernel<<<(H1 * H1 + 255) / 256, 256>>>(conv2_w, w2hi, w2lo, H1 * H1);

    // 2) fc1 (tensor pipe): h = x @ conv1_w^T + b
    gemm_mma3_kernel<<<dim3(H1 / MM_BN, MROWS / MM_BM), 256, MM_SMEM>>>(
        xhi, xlo, w1hi, w1lo, conv1_b, hp, H1, K1);

    // 3) BN1 + relu -> bf16 split
    bn_stats_kernel<<<H1 / 32, 256>>>(hp, st, MROWS, H1);
    bn_apply_relu_cvt_kernel<<<(MROWS * H1 + 255) / 256, 256>>>(hp, st, bn1_g, bn1_b, hhi, hlo, MROWS, H1);

    // 4) fc2 (tensor pipe): s = h @ conv2_w^T + b
    gemm_mma3_kernel<<<dim3(H1 / MM_BN, MROWS / MM_BM), 256, MM_SMEM>>>(
        hhi, hlo, w2hi, w2lo, conv2_b, sp, H1, H1);

    // 5) BN2 + relu (fp32)
    bn_stats_kernel<<<H1 / 32, 256>>>(sp, st, MROWS, H1);
    bn_apply_relu_kernel<<<(MROWS * H1 + 255) / 256, 256>>>(sp, st, bn2_g, bn2_b, MROWS, H1);

    // 6) heads (fp32)
    gemm_abt_kernel<<<dim3(2, 16), 256>>>(sp, cls_w, cls_b, out + OFF_LOGITS, MROWS, NCLS, H1, 0);
    gemm_abt_kernel<<<dim3(6, 16), 256>>>(sp, box_w, box_b, out + OFF_BBOX, MROWS, NCLS * 4, H1, 0);
    softmax_kernel<<<MROWS, 128>>>(out + OFF_LOGITS, out + OFF_PROBS);

    // 7) meta-weight MLP
    gemm_abt_kernel<<<dim3(16, 2), 256>>>(cls_w, tf1_w, tf1_b, mw, NCLS, H1, H1, 1);
    gemm_abt_kernel<<<dim3(4, 2), 256>>>(mw, tf2_w, tf2_b, out + OFF_MW, NCLS, 256, H1, 1);
}

// round 15
// speedup vs baseline: 1.6505x; 1.1666x over previous
#include <cuda_runtime.h>
#include <cuda_fp16.h>
#include <math.h>
#include <stdint.h>

#define BB 2
#define NN 512
#define CC 256
#define POOLP 7
#define NCLS 81
#define MROWS (BB*NN)          // 1024
#define K1 (CC*POOLP*POOLP)    // 12544
#define H1 1024
#define IMGSZ 1024.0f

// ---------------- scratch (device globals; no allocation allowed) ----------------
__device__ __half g_xhi[(size_t)MROWS * K1];
__device__ __half g_xlo[(size_t)MROWS * K1];
__device__ __half g_w1[(size_t)H1 * K1];
__device__ __half g_w2[(size_t)H1 * H1];
__device__ __half g_hhi[(size_t)MROWS * H1];
__device__ __half g_hlo[(size_t)MROWS * H1];
__device__ float g_h[MROWS * H1];           // fc1 pre-BN (fp32)
__device__ float g_s[MROWS * H1];           // fc2 pre/post BN ("shared")
__device__ float g_stats[2 * H1];           // mean, var per feature
__device__ float g_mw1[NCLS * H1];          // MLP intermediate

// ================= PTX helpers (base-target only: sm_80-class) =================
__device__ __forceinline__ uint32_t smem_u32(const void* p) {
    uint32_t a;
    asm("{ .reg .u64 t; cvta.to.shared.u64 t, %1; cvt.u32.u64 %0, t; }" : "=r"(a) : "l"(p));
    return a;
}
__device__ __forceinline__ void cp_async16(uint32_t dst, const void* src) {
    asm volatile("cp.async.cg.shared.global [%0], [%1], 16;" :: "r"(dst), "l"(src) : "memory");
}
__device__ __forceinline__ void ldsm_x4(uint32_t* r, uint32_t addr) {
    asm volatile("ldmatrix.sync.aligned.m8n8.x4.shared.b16 {%0,%1,%2,%3}, [%4];"
                 : "=r"(r[0]), "=r"(r[1]), "=r"(r[2]), "=r"(r[3]) : "r"(addr));
}
__device__ __forceinline__ void mma16816(float* d, const uint32_t* a, const uint32_t* b) {
    asm volatile("mma.sync.aligned.m16n8k16.row.col.f32.f16.f16.f32 "
                 "{%0,%1,%2,%3}, {%4,%5,%6,%7}, {%8,%9}, {%0,%1,%2,%3};"
                 : "+f"(d[0]), "+f"(d[1]), "+f"(d[2]), "+f"(d[3])
                 : "r"(a[0]), "r"(a[1]), "r"(a[2]), "r"(a[3]), "r"(b[0]), "r"(b[1]));
}

// ====== mma.sync 2-pass fp16 GEMM: C[M,N] = (Ahi+Alo)[M,K] @ B[N,K]^T + bias ===
// A split into fp16 hi+lo (~22-bit effective); B single fp16.
// Requires M % 64 == 0, N % 128 == 0, K % 32 == 0.
#define MM_BM 64
#define MM_BN 128
#define MM_BK 32
#define MM_RSTRIDE 80                   // bytes per smem row (32 fp16 + 16B pad)
#define MM_ABYTES (MM_BM * MM_RSTRIDE)  // 5120
#define MM_BBYTES (MM_BN * MM_RSTRIDE)  // 10240
#define MM_BUF (2*MM_ABYTES + MM_BBYTES)    // 20480 per stage (Ahi, Alo, B)
#define MM_STAGES 3
#define MM_SMEM (MM_STAGES*MM_BUF)          // 61440

__global__ void __launch_bounds__(256, 1)
gemm_mma2_kernel(const __half* __restrict__ Ahi, const __half* __restrict__ Alo,
                 const __half* __restrict__ Bf,
                 const float* __restrict__ bias, float* __restrict__ C, int N, int K)
{
    extern __shared__ char smem[];
    uint32_t sb = smem_u32(smem);
    int tid = threadIdx.x;
    int wid = tid >> 5, lane = tid & 31;
    int rowBase = blockIdx.y * MM_BM;
    int colBase = blockIdx.x * MM_BN;
    int warp_m = wid >> 2;      // 0..1  -> 32 rows each (2 m-tiles of 16)
    int warp_n = wid & 3;       // 0..3  -> 32 cols each (4 n-tiles of 8)
    int m_base = warp_m * 32;
    int n_base = warp_n * 32;

    float acc[2][4][4];
    #pragma unroll
    for (int mt = 0; mt < 2; mt++)
        #pragma unroll
        for (int nt = 0; nt < 4; nt++)
            #pragma unroll
            for (int j = 0; j < 4; j++) acc[mt][nt][j] = 0.f;

    int nc = K / MM_BK;

    auto load_chunk = [&](int c, int slot) {
        uint32_t base = sb + (uint32_t)slot * MM_BUF;
        int k0 = c * MM_BK;
        #pragma unroll
        for (int i = 0; i < 2; i++) {                 // A: 512 x 16B segments (hi+lo)
            int id = tid + i * 256;
            int t = id >> 8;                          // 0=hi 1=lo
            int s = id & 255;
            int r = s >> 2, cseg = s & 3;
            const __half* src = (t ? Alo : Ahi) + (size_t)(rowBase + r) * K + k0 + cseg * 8;
            cp_async16(base + (uint32_t)t * MM_ABYTES + (uint32_t)(r * MM_RSTRIDE + cseg * 16), src);
        }
        #pragma unroll
        for (int i = 0; i < 2; i++) {                 // B: 512 x 16B segments (single)
            int id = tid + i * 256;
            int r = id >> 2, cseg = id & 3;
            const __half* src = Bf + (size_t)(colBase + r) * K + k0 + cseg * 8;
            cp_async16(base + 2 * MM_ABYTES + (uint32_t)(r * MM_RSTRIDE + cseg * 16), src);
        }
        asm volatile("cp.async.commit_group;" ::: "memory");
    };

    // prologue: 2-deep prefetch
    load_chunk(0, 0);
    load_chunk(1, 1);

    // hoisted fragment address components
    int arow = m_base + (lane & 15);
    uint32_t acol_base = (uint32_t)(((lane >> 4) << 3) * 2);
    int brow = n_base + ((lane >= 16) ? 8 : 0) + (lane & 7);
    uint32_t bcol_base = (uint32_t)((((lane >> 3) & 1) << 3) * 2);

    for (int c = 0; c < nc; c++) {
        if (c + 1 < nc) {
            asm volatile("cp.async.wait_group 1;" ::: "memory");
        } else {
            asm volatile("cp.async.wait_group 0;" ::: "memory");
        }
        __syncthreads();   // chunk c visible; all warps done with slot (c+2)%3's old data

        if (c + 2 < nc) load_chunk(c + 2, (c + 2) % MM_STAGES);

        uint32_t abase = sb + (uint32_t)(c % MM_STAGES) * MM_BUF;
        uint32_t bbase = abase + 2 * MM_ABYTES;

        // ---- preload ALL fragments for this chunk (both k16 halves) ----
        uint32_t ahi[2][2][4], alo[2][2][4];   // [ks][mt][4]
        uint32_t bf[2][4][2];                  // [ks][nt][2]
        #pragma unroll
        for (int ks = 0; ks < 2; ks++) {
            uint32_t acol = acol_base + (uint32_t)(ks * 32);
            #pragma unroll
            for (int mt = 0; mt < 2; mt++) {
                uint32_t addr = abase + (uint32_t)((arow + mt * 16) * MM_RSTRIDE) + acol;
                ldsm_x4(ahi[ks][mt], addr);
                ldsm_x4(alo[ks][mt], addr + MM_ABYTES);
            }
            uint32_t bcol = bcol_base + (uint32_t)(ks * 32);
            #pragma unroll
            for (int np = 0; np < 2; np++) {
                uint32_t addr = bbase + (uint32_t)((brow + np * 16) * MM_RSTRIDE) + bcol;
                uint32_t r4[4];
                ldsm_x4(r4, addr);
                bf[ks][np*2][0] = r4[0]; bf[ks][np*2][1] = r4[1];
                bf[ks][np*2+1][0] = r4[2]; bf[ks][np*2+1][1] = r4[3];
            }
        }

        // ---- 2 passes of 8 independent MMAs per k16 half ----
        #pragma unroll
        for (int ks = 0; ks < 2; ks++) {
            #pragma unroll
            for (int mt = 0; mt < 2; mt++)
                #pragma unroll
                for (int nt = 0; nt < 4; nt++)
                    mma16816(acc[mt][nt], ahi[ks][mt], bf[ks][nt]);
            #pragma unroll
            for (int mt = 0; mt < 2; mt++)
                #pragma unroll
                for (int nt = 0; nt < 4; nt++)
                    mma16816(acc[mt][nt], alo[ks][mt], bf[ks][nt]);
        }
        // no trailing sync: next iteration's sync protects slot reuse
    }

    // ---- epilogue: bias + store ----
    int g = lane >> 2, t2 = (lane & 3) * 2;
    #pragma unroll
    for (int mt = 0; mt < 2; mt++) {
        int row0 = rowBase + m_base + mt * 16 + g;
        #pragma unroll
        for (int nt = 0; nt < 4; nt++) {
            int col = colBase + n_base + nt * 8 + t2;
            float b0 = bias[col], b1 = bias[col + 1];
            float2* p0 = reinterpret_cast<float2*>(&C[(size_t)row0 * N + col]);
            float2* p1 = reinterpret_cast<float2*>(&C[(size_t)(row0 + 8) * N + col]);
            *p0 = make_float2(acc[mt][nt][0] + b0, acc[mt][nt][1] + b1);
            *p1 = make_float2(acc[mt][nt][2] + b0, acc[mt][nt][3] + b1);
        }
    }
}

// ---------------- ROI align -> fp16 hi/lo directly ----------------
__global__ void roi_align_kernel(const float* __restrict__ p2, const float* __restrict__ p3,
                                 const float* __restrict__ p4, const float* __restrict__ p5,
                                 const float* __restrict__ rois,
                                 __half* __restrict__ Xhi, __half* __restrict__ Xlo)
{
    int n = blockIdx.x;
    const float* roi = rois + (size_t)n * 4;
    float x1 = roi[0], y1 = roi[1], x2 = roi[2], y2 = roi[3];
    float area = (y2 - y1) * (x2 - x1);
    float lf = rintf(log2f(sqrtf(area) / 224.0f)) + 4.0f;   // half-to-even like jnp.round
    lf = fminf(fmaxf(lf, 2.0f), 5.0f);
    int lvl = (int)lf;

    const float* fm; int H;
    if (lvl == 2)      { fm = p2; H = 256; }
    else if (lvl == 3) { fm = p3; H = 128; }
    else if (lvl == 4) { fm = p4; H = 64;  }
    else               { fm = p5; H = 32;  }
    int W = H;

    float ny1 = y1 / IMGSZ, nx1 = x1 / IMGSZ, ny2 = y2 / IMGSZ, nx2 = x2 / IMGSZ;

    __shared__ int   s_y0[POOLP], s_y1[POOLP], s_x0[POOLP], s_x1[POOLP];
    __shared__ float s_ly[POOLP], s_lx[POOLP];

    int t = threadIdx.x;
    if (t < POOLP) {
        float g = (float)t / (float)(POOLP - 1);
        float ys = (ny1 + g * (ny2 - ny1)) * (float)(H - 1);
        float y0f = floorf(ys);
        s_ly[t] = ys - y0f;
        s_y0[t] = (int)fminf(fmaxf(y0f, 0.0f), (float)(H - 1));
        s_y1[t] = (int)fminf(fmaxf(y0f + 1.0f, 0.0f), (float)(H - 1));
    } else if (t < 2 * POOLP) {
        int j = t - POOLP;
        float g = (float)j / (float)(POOLP - 1);
        float xs = (nx1 + g * (nx2 - nx1)) * (float)(W - 1);
        float x0f = floorf(xs);
        s_lx[j] = xs - x0f;
        s_x0[j] = (int)fminf(fmaxf(x0f, 0.0f), (float)(W - 1));
        s_x1[j] = (int)fminf(fmaxf(x0f + 1.0f, 0.0f), (float)(W - 1));
    }
    __syncthreads();

    int HW = H * W;
    for (int idx = threadIdx.x; idx < K1; idx += blockDim.x) {
        int c  = idx / (POOLP * POOLP);
        int p  = idx % (POOLP * POOLP);
        int py = p / POOLP, px = p % POOLP;
        const float* plane = fm + (size_t)c * HW;
        float ly = s_ly[py], lx = s_lx[px];
        int y0 = s_y0[py], y1i = s_y1[py], x0 = s_x0[px], x1i = s_x1[px];
        float v00 = plane[y0  * W + x0 ];
        float v01 = plane[y0  * W + x1i];
        float v10 = plane[y1i * W + x0 ];
        float v11 = plane[y1i * W + x1i];
        float val = v00 * (1.0f - ly) * (1.0f - lx)
                  + v01 * (1.0f - ly) * lx
                  + v10 * ly * (1.0f - lx)
                  + v11 * ly * lx;
        __half h = __float2half_rn(val);
        Xhi[(size_t)n * K1 + idx] = h;
        Xlo[(size_t)n * K1 + idx] = __float2half_rn(val - __half2float(h));
    }
}

// ---------------- fp32 -> fp16 single ----------------
__global__ void cvt_half_kernel(const float* __restrict__ src, __half* __restrict__ dst, int n)
{
    int i = blockIdx.x * blockDim.x + threadIdx.x;
    if (i < n) dst[i] = __float2half_rn(src[i]);
}

// ---------------- fp32 tiled GEMM for small heads: C = A @ B^T + bias ----------------
#define BM 64
#define BN 64
#define BK 16
__global__ void gemm_abt_kernel(const float* __restrict__ A, const float* __restrict__ B,
                                const float* __restrict__ bias, float* __restrict__ C,
                                int M, int N, int K, int act)
{
    __shared__ float As[BK][BM];
    __shared__ float Bs[BK][BN];

    int tid = threadIdx.x;
    int tx = tid & 15;
    int ty = tid >> 4;
    int rowBase = blockIdx.y * BM;
    int colBase = blockIdx.x * BN;
    int lr = tid >> 2;
    int lk = (tid & 3) * 4;

    float acc[4][4] = {{0.f}};

    for (int k0 = 0; k0 < K; k0 += BK) {
        float4 av = make_float4(0.f, 0.f, 0.f, 0.f);
        int ar = rowBase + lr;
        if (ar < M) av = *reinterpret_cast<const float4*>(&A[(size_t)ar * K + k0 + lk]);
        As[lk + 0][lr] = av.x; As[lk + 1][lr] = av.y;
        As[lk + 2][lr] = av.z; As[lk + 3][lr] = av.w;

        float4 bv = make_float4(0.f, 0.f, 0.f, 0.f);
        int br = colBase + lr;
        if (br < N) bv = *reinterpret_cast<const float4*>(&B[(size_t)br * K + k0 + lk]);
        Bs[lk + 0][lr] = bv.x; Bs[lk + 1][lr] = bv.y;
        Bs[lk + 2][lr] = bv.z; Bs[lk + 3][lr] = bv.w;

        __syncthreads();

        #pragma unroll
        for (int k = 0; k < BK; k++) {
            float4 a = *reinterpret_cast<const float4*>(&As[k][ty * 4]);
            float4 b = *reinterpret_cast<const float4*>(&Bs[k][tx * 4]);
            float aa[4] = {a.x, a.y, a.z, a.w};
            float bb[4] = {b.x, b.y, b.z, b.w};
            #pragma unroll
            for (int i = 0; i < 4; i++)
                #pragma unroll
                for (int j = 0; j < 4; j++)
                    acc[i][j] = fmaf(aa[i], bb[j], acc[i][j]);
        }
        __syncthreads();
    }

    #pragma unroll
    for (int i = 0; i < 4; i++) {
        int row = rowBase + ty * 4 + i;
        if (row >= M) continue;
        #pragma unroll
        for (int j = 0; j < 4; j++) {
            int col = colBase + tx * 4 + j;
            if (col >= N) continue;
            float v = acc[i][j] + bias[col];
            if (act == 1) v = (v >= 0.f) ? v : 0.01f * v;
            C[(size_t)row * N + col] = v;
        }
    }
}

// ---------------- batch-norm stats (coalesced: 32 cols x 8 rows per block) ----------------
__global__ void bn_stats_kernel(const float* __restrict__ Hm, float* __restrict__ stats,
                                int M, int N)
{
    int x = threadIdx.x & 31, y = threadIdx.x >> 5;   // 256 threads
    int col = blockIdx.x * 32 + x;
    float s = 0.f, s2 = 0.f;
    for (int r = y; r < M; r += 8) {
        float v = Hm[(size_t)r * N + col];
        s += v; s2 += v * v;
    }
    __shared__ float sh[8][32], sh2[8][32];
    sh[y][x] = s; sh2[y][x] = s2;
    __syncthreads();
    if (y == 0) {
        #pragma unroll
        for (int i = 1; i < 8; i++) { s += sh[i][x]; s2 += sh2[i][x]; }
        float m = s / (float)M;
        stats[col]     = m;
        stats[N + col] = s2 / (float)M - m * m;
    }
}

// BN1: apply + relu, write fp16 hi/lo (feeds fp16 GEMM2)
__global__ void bn_apply_relu_cvt_kernel(const float* __restrict__ Hm, const float* __restrict__ stats,
                                         const float* __restrict__ gam, const float* __restrict__ bet,
                                         __half* __restrict__ hi, __half* __restrict__ lo,
                                         int M, int N)
{
    int idx = blockIdx.x * blockDim.x + threadIdx.x;
    if (idx >= M * N) return;
    int col = idx % N;
    float m = stats[col], v = stats[N + col];
    float h = (Hm[idx] - m) * rsqrtf(v + 0.001f) * gam[col] + bet[col];
    h = fmaxf(h, 0.f);
    __half hh = __float2half_rn(h);
    hi[idx] = hh;
    lo[idx] = __float2half_rn(h - __half2float(hh));
}

// BN2: apply + relu in-place fp32 (feeds fp32 heads)
__global__ void bn_apply_relu_kernel(float* __restrict__ Hm, const float* __restrict__ stats,
                                     const float* __restrict__ gam, const float* __restrict__ bet,
                                     int M, int N)
{
    int idx = blockIdx.x * blockDim.x + threadIdx.x;
    if (idx >= M * N) return;
    int col = idx % N;
    float m = stats[col], v = stats[N + col];
    float h = (Hm[idx] - m) * rsqrtf(v + 0.001f) * gam[col] + bet[col];
    Hm[idx] = fmaxf(h, 0.f);
}

// ---------------- softmax over 81 classes per row ----------------
__global__ void softmax_kernel(const float* __restrict__ logits, float* __restrict__ probs)
{
    int row = blockIdx.x;
    int t = threadIdx.x;   // 128 threads
    __shared__ float red[128];
    float v = (t < NCLS) ? logits[(size_t)row * NCLS + t] : -INFINITY;
    red[t] = v;
    __syncthreads();
    for (int o = 64; o > 0; o >>= 1) {
        if (t < o) red[t] = fmaxf(red[t], red[t + o]);
        __syncthreads();
    }
    float mx = red[0];
    __syncthreads();
    float e = (t < NCLS) ? expf(v - mx) : 0.f;
    red[t] = e;
    __syncthreads();
    for (int o = 64; o > 0; o >>= 1) {
        if (t < o) red[t] += red[t + o];
        __syncthreads();
    }
    if (t < NCLS) probs[(size_t)row * NCLS + t] = e / red[0];
}

// ---------------- launch ----------------
extern "C" void kernel_launch(void* const* d_in, const int* in_sizes, int n_in,
                              void* d_out, int out_size)
{
    const float* p2      = (const float*)d_in[0];
    const float* p3      = (const float*)d_in[1];
    const float* p4      = (const float*)d_in[2];
    const float* p5      = (const float*)d_in[3];
    const float* rois    = (const float*)d_in[4];
    const float* conv1_w = (const float*)d_in[5];
    const float* conv1_b = (const float*)d_in[6];
    const float* bn1_g   = (const float*)d_in[7];
    const float* bn1_b   = (const float*)d_in[8];
    const float* conv2_w = (const float*)d_in[9];
    const float* conv2_b = (const float*)d_in[10];
    const float* bn2_g   = (const float*)d_in[11];
    const float* bn2_b   = (const float*)d_in[12];
    const float* cls_w   = (const float*)d_in[13];
    const float* cls_b   = (const float*)d_in[14];
    const float* box_w   = (const float*)d_in[15];
    const float* box_b   = (const float*)d_in[16];
    const float* tf1_w   = (const float*)d_in[17];
    const float* tf1_b   = (const float*)d_in[18];
    const float* tf2_w   = (const float*)d_in[19];
    const float* tf2_b   = (const float*)d_in[20];
    float* out = (float*)d_out;

    static __half *xhi=nullptr,*xlo=nullptr,*w1=nullptr,*w2=nullptr,*hhi=nullptr,*hlo=nullptr;
    static float *hp=nullptr, *sp=nullptr, *st=nullptr, *mw=nullptr;
    if (!hp) {
        cudaGetSymbolAddress((void**)&xhi, g_xhi);
        cudaGetSymbolAddress((void**)&xlo, g_xlo);
        cudaGetSymbolAddress((void**)&w1, g_w1);
        cudaGetSymbolAddress((void**)&w2, g_w2);
        cudaGetSymbolAddress((void**)&hhi, g_hhi);
        cudaGetSymbolAddress((void**)&hlo, g_hlo);
        cudaGetSymbolAddress((void**)&hp, g_h);
        cudaGetSymbolAddress((void**)&sp, g_s);
        cudaGetSymbolAddress((void**)&st, g_stats);
        cudaGetSymbolAddress((void**)&mw, g_mw1);
        cudaFuncSetAttribute(gemm_mma2_kernel, cudaFuncAttributeMaxDynamicSharedMemorySize, MM_SMEM);
    }

    const int OFF_LOGITS = 0;
    const int OFF_PROBS  = MROWS * NCLS;                 // 82944
    const int OFF_BBOX   = 2 * MROWS * NCLS;             // 165888
    const int OFF_MW     = OFF_BBOX + MROWS * NCLS * 4;  // 497664

    // 1) ROI align -> xhi/xlo [1024, 12544] (fp16 split)
    roi_align_kernel<<<MROWS, 256>>>(p2, p3, p4, p5, rois, xhi, xlo);

    // weight conversions (fp32 -> fp16 single)
    cvt_half_kernel<<<(H1 * K1 + 255) / 256, 256>>>(conv1_w, w1, H1 * K1);
    cvt_half_kernel<<<(H1 * H1 + 255) / 256, 256>>>(conv2_w, w2, H1 * H1);

    // 2) fc1 (tensor pipe, 2-pass fp16): h = x @ conv1_w^T + b
    gemm_mma2_kernel<<<dim3(H1 / MM_BN, MROWS / MM_BM), 256, MM_SMEM>>>(
        xhi, xlo, w1, conv1_b, hp, H1, K1);

    // 3) BN1 + relu -> fp16 split
    bn_stats_kernel<<<H1 / 32, 256>>>(hp, st, MROWS, H1);
    bn_apply_relu_cvt_kernel<<<(MROWS * H1 + 255) / 256, 256>>>(hp, st, bn1_g, bn1_b, hhi, hlo, MROWS, H1);

    // 4) fc2 (tensor pipe): s = h @ conv2_w^T + b
    gemm_mma2_kernel<<<dim3(H1 / MM_BN, MROWS / MM_BM), 256, MM_SMEM>>>(
        hhi, hlo, w2, conv2_b, sp, H1, H1);

    // 5) BN2 + relu (fp32)
    bn_stats_kernel<<<H1 / 32, 256>>>(sp, st, MROWS, H1);
    bn_apply_relu_kernel<<<(MROWS * H1 + 255) / 256, 256>>>(sp, st, bn2_g, bn2_b, MROWS, H1);

    // 6) heads (fp32)
    gemm_abt_kernel<<<dim3(2, 16), 256>>>(sp, cls_w, cls_b, out + OFF_LOGITS, MROWS, NCLS, H1, 0);
    gemm_abt_kernel<<<dim3(6, 16), 256>>>(sp, box_w, box_b, out + OFF_BBOX, MROWS, NCLS * 4, H1, 0);
    softmax_kernel<<<MROWS, 128>>>(out + OFF_LOGITS, out + OFF_PROBS);

    // 7) meta-weight MLP
    gemm_abt_kernel<<<dim3(16, 2), 256>>>(cls_w, tf1_w, tf1_b, mw, NCLS, H1, H1, 1);
    gemm_abt_kernel<<<dim3(4, 2), 256>>>(mw, tf2_w, tf2_b, out + OFF_MW, NCLS, 256, H1, 1);
}

// round 16
// speedup vs baseline: 2.0457x; 1.2394x over previous
#include <cuda_runtime.h>
#include <cuda_fp16.h>
#include <math.h>
#include <stdint.h>

#define BB 2
#define NN 512
#define CC 256
#define POOLP 7
#define NCLS 81
#define MROWS (BB*NN)          // 1024
#define K1 (CC*POOLP*POOLP)    // 12544
#define H1 1024
#define IMGSZ 1024.0f
#define NHEAD 512              // padded cls(81)+box(324) rows

// ---------------- scratch (device globals; no allocation allowed) ----------------
__device__ __half g_xhi[(size_t)MROWS * K1];
__device__ __half g_xlo[(size_t)MROWS * K1];
__device__ __half g_w1[(size_t)H1 * K1];
__device__ __half g_w2[(size_t)H1 * H1];
__device__ __half g_wcat[(size_t)NHEAD * H1];
__device__ float  g_bcat[NHEAD];
__device__ __half g_hhi[(size_t)MROWS * H1];
__device__ __half g_hlo[(size_t)MROWS * H1];
__device__ float g_h[MROWS * H1];           // fc1 pre-BN (fp32)
__device__ float g_s[MROWS * H1];           // fc2 pre-BN / head output scratch
__device__ float g_stats[2 * H1];           // mean, var per feature
__device__ float g_mw1[NCLS * H1];          // MLP intermediate

// ================= PTX helpers (base-target only: sm_80-class) =================
__device__ __forceinline__ uint32_t smem_u32(const void* p) {
    uint32_t a;
    asm("{ .reg .u64 t; cvta.to.shared.u64 t, %1; cvt.u32.u64 %0, t; }" : "=r"(a) : "l"(p));
    return a;
}
__device__ __forceinline__ void cp_async16(uint32_t dst, const void* src) {
    asm volatile("cp.async.cg.shared.global [%0], [%1], 16;" :: "r"(dst), "l"(src) : "memory");
}
__device__ __forceinline__ void ldsm_x4(uint32_t* r, uint32_t addr) {
    asm volatile("ldmatrix.sync.aligned.m8n8.x4.shared.b16 {%0,%1,%2,%3}, [%4];"
                 : "=r"(r[0]), "=r"(r[1]), "=r"(r[2]), "=r"(r[3]) : "r"(addr));
}
__device__ __forceinline__ void mma16816(float* d, const uint32_t* a, const uint32_t* b) {
    asm volatile("mma.sync.aligned.m16n8k16.row.col.f32.f16.f16.f32 "
                 "{%0,%1,%2,%3}, {%4,%5,%6,%7}, {%8,%9}, {%0,%1,%2,%3};"
                 : "+f"(d[0]), "+f"(d[1]), "+f"(d[2]), "+f"(d[3])
                 : "r"(a[0]), "r"(a[1]), "r"(a[2]), "r"(a[3]), "r"(b[0]), "r"(b[1]));
}

// ====== mma.sync 2-pass fp16 GEMM: C[M,N] = (Ahi+Alo)[M,K] @ B[N,K]^T + bias ===
// Requires M % 64 == 0, N % 128 == 0, K % 64 == 0.
#define MM_BM 64
#define MM_BN 128
#define MM_BK 64
#define MM_RSTRIDE 144                  // bytes per smem row (64 fp16 + 16B pad)
#define MM_ABYTES (MM_BM * MM_RSTRIDE)  // 9216
#define MM_BBYTES (MM_BN * MM_RSTRIDE)  // 18432
#define MM_BUF (2*MM_ABYTES + MM_BBYTES)    // 36864 per stage (Ahi, Alo, B)
#define MM_STAGES 3
#define MM_SMEM (MM_STAGES*MM_BUF)          // 110592

__global__ void __launch_bounds__(256, 1)
gemm_mma2_kernel(const __half* __restrict__ Ahi, const __half* __restrict__ Alo,
                 const __half* __restrict__ Bf,
                 const float* __restrict__ bias, float* __restrict__ C, int N, int K)
{
    extern __shared__ char smem[];
    uint32_t sb = smem_u32(smem);
    int tid = threadIdx.x;
    int wid = tid >> 5, lane = tid & 31;
    int rowBase = blockIdx.y * MM_BM;
    int colBase = blockIdx.x * MM_BN;
    int warp_m = wid >> 2;      // 0..1  -> 32 rows each (2 m-tiles of 16)
    int warp_n = wid & 3;       // 0..3  -> 32 cols each (4 n-tiles of 8)
    int m_base = warp_m * 32;
    int n_base = warp_n * 32;

    float acc[2][4][4];
    #pragma unroll
    for (int mt = 0; mt < 2; mt++)
        #pragma unroll
        for (int nt = 0; nt < 4; nt++)
            #pragma unroll
            for (int j = 0; j < 4; j++) acc[mt][nt][j] = 0.f;

    int nc = K / MM_BK;

    auto load_chunk = [&](int c, int slot) {
        uint32_t base = sb + (uint32_t)slot * MM_BUF;
        int k0 = c * MM_BK;
        #pragma unroll
        for (int i = 0; i < 4; i++) {                 // A: 1024 x 16B segments (hi+lo)
            int id = tid + i * 256;
            int t = id >> 9;                          // 0=hi 1=lo
            int s = id & 511;
            int r = s >> 3, cseg = s & 7;
            const __half* src = (t ? Alo : Ahi) + (size_t)(rowBase + r) * K + k0 + cseg * 8;
            cp_async16(base + (uint32_t)t * MM_ABYTES + (uint32_t)(r * MM_RSTRIDE + cseg * 16), src);
        }
        #pragma unroll
        for (int i = 0; i < 4; i++) {                 // B: 1024 x 16B segments (single)
            int id = tid + i * 256;
            int r = id >> 3, cseg = id & 7;
            const __half* src = Bf + (size_t)(colBase + r) * K + k0 + cseg * 8;
            cp_async16(base + 2 * MM_ABYTES + (uint32_t)(r * MM_RSTRIDE + cseg * 16), src);
        }
        asm volatile("cp.async.commit_group;" ::: "memory");
    };

    // prologue: 2-deep prefetch
    load_chunk(0, 0);
    load_chunk(1, 1);

    // hoisted fragment address components
    int arow = m_base + (lane & 15);
    uint32_t acol_base = (uint32_t)(((lane >> 4) << 3) * 2);
    int brow = n_base + ((lane >= 16) ? 8 : 0) + (lane & 7);
    uint32_t bcol_base = (uint32_t)((((lane >> 3) & 1) << 3) * 2);

    for (int c = 0; c < nc; c++) {
        if (c + 1 < nc) {
            asm volatile("cp.async.wait_group 1;" ::: "memory");
        } else {
            asm volatile("cp.async.wait_group 0;" ::: "memory");
        }
        __syncthreads();   // chunk c visible; all warps done with slot (c+2)%3's old data

        if (c + 2 < nc) load_chunk(c + 2, (c + 2) % MM_STAGES);

        uint32_t abase = sb + (uint32_t)(c % MM_STAGES) * MM_BUF;
        uint32_t bbase = abase + 2 * MM_ABYTES;

        #pragma unroll
        for (int kh = 0; kh < 2; kh++) {
            // ---- preload fragments for this k32 half (2 k16 quarters) ----
            uint32_t ahi[2][2][4], alo[2][2][4];   // [ks][mt][4]
            uint32_t bf[2][4][2];                  // [ks][nt][2]
            #pragma unroll
            for (int ks = 0; ks < 2; ks++) {
                uint32_t acol = acol_base + (uint32_t)(kh * 64 + ks * 32);
                #pragma unroll
                for (int mt = 0; mt < 2; mt++) {
                    uint32_t addr = abase + (uint32_t)((arow + mt * 16) * MM_RSTRIDE) + acol;
                    ldsm_x4(ahi[ks][mt], addr);
                    ldsm_x4(alo[ks][mt], addr + MM_ABYTES);
                }
                uint32_t bcol = bcol_base + (uint32_t)(kh * 64 + ks * 32);
                #pragma unroll
                for (int np = 0; np < 2; np++) {
                    uint32_t addr = bbase + (uint32_t)((brow + np * 16) * MM_RSTRIDE) + bcol;
                    uint32_t r4[4];
                    ldsm_x4(r4, addr);
                    bf[ks][np*2][0] = r4[0]; bf[ks][np*2][1] = r4[1];
                    bf[ks][np*2+1][0] = r4[2]; bf[ks][np*2+1][1] = r4[3];
                }
            }
            // ---- 2 passes of 8 independent MMAs per k16 quarter ----
            #pragma unroll
            for (int ks = 0; ks < 2; ks++) {
                #pragma unroll
                for (int mt = 0; mt < 2; mt++)
                    #pragma unroll
                    for (int nt = 0; nt < 4; nt++)
                        mma16816(acc[mt][nt], ahi[ks][mt], bf[ks][nt]);
                #pragma unroll
                for (int mt = 0; mt < 2; mt++)
                    #pragma unroll
                    for (int nt = 0; nt < 4; nt++)
                        mma16816(acc[mt][nt], alo[ks][mt], bf[ks][nt]);
            }
        }
        // no trailing sync: next iteration's sync protects slot reuse
    }

    // ---- epilogue: bias + store ----
    int g = lane >> 2, t2 = (lane & 3) * 2;
    #pragma unroll
    for (int mt = 0; mt < 2; mt++) {
        int row0 = rowBase + m_base + mt * 16 + g;
        #pragma unroll
        for (int nt = 0; nt < 4; nt++) {
            int col = colBase + n_base + nt * 8 + t2;
            float b0 = bias[col], b1 = bias[col + 1];
            float2* p0 = reinterpret_cast<float2*>(&C[(size_t)row0 * N + col]);
            float2* p1 = reinterpret_cast<float2*>(&C[(size_t)(row0 + 8) * N + col]);
            *p0 = make_float2(acc[mt][nt][0] + b0, acc[mt][nt][1] + b1);
            *p1 = make_float2(acc[mt][nt][2] + b0, acc[mt][nt][3] + b1);
        }
    }
}

// ---------------- ROI align -> fp16 hi/lo directly ----------------
__global__ void roi_align_kernel(const float* __restrict__ p2, const float* __restrict__ p3,
                                 const float* __restrict__ p4, const float* __restrict__ p5,
                                 const float* __restrict__ rois,
                                 __half* __restrict__ Xhi, __half* __restrict__ Xlo)
{
    int n = blockIdx.x;
    const float* roi = rois + (size_t)n * 4;
    float x1 = roi[0], y1 = roi[1], x2 = roi[2], y2 = roi[3];
    float area = (y2 - y1) * (x2 - x1);
    float lf = rintf(log2f(sqrtf(area) / 224.0f)) + 4.0f;   // half-to-even like jnp.round
    lf = fminf(fmaxf(lf, 2.0f), 5.0f);
    int lvl = (int)lf;

    const float* fm; int H;
    if (lvl == 2)      { fm = p2; H = 256; }
    else if (lvl == 3) { fm = p3; H = 128; }
    else if (lvl == 4) { fm = p4; H = 64;  }
    else               { fm = p5; H = 32;  }
    int W = H;

    float ny1 = y1 / IMGSZ, nx1 = x1 / IMGSZ, ny2 = y2 / IMGSZ, nx2 = x2 / IMGSZ;

    __shared__ int   s_y0[POOLP], s_y1[POOLP], s_x0[POOLP], s_x1[POOLP];
    __shared__ float s_ly[POOLP], s_lx[POOLP];

    int t = threadIdx.x;
    if (t < POOLP) {
        float g = (float)t / (float)(POOLP - 1);
        float ys = (ny1 + g * (ny2 - ny1)) * (float)(H - 1);
        float y0f = floorf(ys);
        s_ly[t] = ys - y0f;
        s_y0[t] = (int)fminf(fmaxf(y0f, 0.0f), (float)(H - 1));
        s_y1[t] = (int)fminf(fmaxf(y0f + 1.0f, 0.0f), (float)(H - 1));
    } else if (t < 2 * POOLP) {
        int j = t - POOLP;
        float g = (float)j / (float)(POOLP - 1);
        float xs = (nx1 + g * (nx2 - nx1)) * (float)(W - 1);
        float x0f = floorf(xs);
        s_lx[j] = xs - x0f;
        s_x0[j] = (int)fminf(fmaxf(x0f, 0.0f), (float)(W - 1));
        s_x1[j] = (int)fminf(fmaxf(x0f + 1.0f, 0.0f), (float)(W - 1));
    }
    __syncthreads();

    int HW = H * W;
    for (int idx = threadIdx.x; idx < K1; idx += blockDim.x) {
        int c  = idx / (POOLP * POOLP);
        int p  = idx % (POOLP * POOLP);
        int py = p / POOLP, px = p % POOLP;
        const float* plane = fm + (size_t)c * HW;
        float ly = s_ly[py], lx = s_lx[px];
        int y0 = s_y0[py], y1i = s_y1[py], x0 = s_x0[px], x1i = s_x1[px];
        float v00 = plane[y0  * W + x0 ];
        float v01 = plane[y0  * W + x1i];
        float v10 = plane[y1i * W + x0 ];
        float v11 = plane[y1i * W + x1i];
        float val = v00 * (1.0f - ly) * (1.0f - lx)
                  + v01 * (1.0f - ly) * lx
                  + v10 * ly * (1.0f - lx)
                  + v11 * ly * lx;
        __half h = __float2half_rn(val);
        Xhi[(size_t)n * K1 + idx] = h;
        Xlo[(size_t)n * K1 + idx] = __float2half_rn(val - __half2float(h));
    }
}

// ---------------- fp32 -> fp16 single ----------------
__global__ void cvt_half_kernel(const float* __restrict__ src, __half* __restrict__ dst, int n)
{
    int i = blockIdx.x * blockDim.x + threadIdx.x;
    if (i < n) dst[i] = __float2half_rn(src[i]);
}

// ---------------- build padded concat head weights (cls 81 + box 324 + 0-pad) --
__global__ void build_wcat_kernel(const float* __restrict__ cls_w, const float* __restrict__ box_w,
                                  const float* __restrict__ cls_b, const float* __restrict__ box_b,
                                  __half* __restrict__ wcat, float* __restrict__ bcat)
{
    int idx = blockIdx.x * blockDim.x + threadIdx.x;
    if (idx >= NHEAD * H1) return;
    int r = idx >> 10, k = idx & (H1 - 1);
    float v = 0.f;
    if (r < NCLS) v = cls_w[r * H1 + k];
    else if (r < NCLS * 5) v = box_w[(r - NCLS) * H1 + k];
    wcat[idx] = __float2half_rn(v);
    if (k == 0) bcat[r] = (r < NCLS) ? cls_b[r] : ((r < NCLS * 5) ? box_b[r - NCLS] : 0.f);
}

// ---------------- split head output into logits / bbox ----------------
__global__ void split_heads_kernel(const float* __restrict__ C, float* __restrict__ logits,
                                   float* __restrict__ bbox)
{
    int idx = blockIdx.x * blockDim.x + threadIdx.x;
    if (idx >= MROWS * NCLS * 5) return;          // 405 per row
    int row = idx / (NCLS * 5), c = idx % (NCLS * 5);
    float v = C[(size_t)row * NHEAD + c];
    if (c < NCLS) logits[(size_t)row * NCLS + c] = v;
    else          bbox[(size_t)row * NCLS * 4 + (c - NCLS)] = v;
}

// ---------------- fp32 tiled GEMM for small MLP: C = A @ B^T + bias ----------------
#define BM 64
#define BN 64
#define BK 16
__global__ void gemm_abt_kernel(const float* __restrict__ A, const float* __restrict__ B,
                                const float* __restrict__ bias, float* __restrict__ C,
                                int M, int N, int K, int act)
{
    __shared__ float As[BK][BM];
    __shared__ float Bs[BK][BN];

    int tid = threadIdx.x;
    int tx = tid & 15;
    int ty = tid >> 4;
    int rowBase = blockIdx.y * BM;
    int colBase = blockIdx.x * BN;
    int lr = tid >> 2;
    int lk = (tid & 3) * 4;

    float acc[4][4] = {{0.f}};

    for (int k0 = 0; k0 < K; k0 += BK) {
        float4 av = make_float4(0.f, 0.f, 0.f, 0.f);
        int ar = rowBase + lr;
        if (ar < M) av = *reinterpret_cast<const float4*>(&A[(size_t)ar * K + k0 + lk]);
        As[lk + 0][lr] = av.x; As[lk + 1][lr] = av.y;
        As[lk + 2][lr] = av.z; As[lk + 3][lr] = av.w;

        float4 bv = make_float4(0.f, 0.f, 0.f, 0.f);
        int br = colBase + lr;
        if (br < N) bv = *reinterpret_cast<const float4*>(&B[(size_t)br * K + k0 + lk]);
        Bs[lk + 0][lr] = bv.x; Bs[lk + 1][lr] = bv.y;
        Bs[lk + 2][lr] = bv.z; Bs[lk + 3][lr] = bv.w;

        __syncthreads();

        #pragma unroll
        for (int k = 0; k < BK; k++) {
            float4 a = *reinterpret_cast<const float4*>(&As[k][ty * 4]);
            float4 b = *reinterpret_cast<const float4*>(&Bs[k][tx * 4]);
            float aa[4] = {a.x, a.y, a.z, a.w};
            float bb[4] = {b.x, b.y, b.z, b.w};
            #pragma unroll
            for (int i = 0; i < 4; i++)
                #pragma unroll
                for (int j = 0; j < 4; j++)
                    acc[i][j] = fmaf(aa[i], bb[j], acc[i][j]);
        }
        __syncthreads();
    }

    #pragma unroll
    for (int i = 0; i < 4; i++) {
        int row = rowBase + ty * 4 + i;
        if (row >= M) continue;
        #pragma unroll
        for (int j = 0; j < 4; j++) {
            int col = colBase + tx * 4 + j;
            if (col >= N) continue;
            float v = acc[i][j] + bias[col];
            if (act == 1) v = (v >= 0.f) ? v : 0.01f * v;
            C[(size_t)row * N + col] = v;
        }
    }
}

// ---------------- batch-norm stats (coalesced: 32 cols x 8 rows per block) ----------------
__global__ void bn_stats_kernel(const float* __restrict__ Hm, float* __restrict__ stats,
                                int M, int N)
{
    int x = threadIdx.x & 31, y = threadIdx.x >> 5;   // 256 threads
    int col = blockIdx.x * 32 + x;
    float s = 0.f, s2 = 0.f;
    for (int r = y; r < M; r += 8) {
        float v = Hm[(size_t)r * N + col];
        s += v; s2 += v * v;
    }
    __shared__ float sh[8][32], sh2[8][32];
    sh[y][x] = s; sh2[y][x] = s2;
    __syncthreads();
    if (y == 0) {
        #pragma unroll
        for (int i = 1; i < 8; i++) { s += sh[i][x]; s2 += sh2[i][x]; }
        float m = s / (float)M;
        stats[col]     = m;
        stats[N + col] = s2 / (float)M - m * m;
    }
}

// BN apply + relu, write fp16 hi/lo (feeds fp16 GEMMs)
__global__ void bn_apply_relu_cvt_kernel(const float* __restrict__ Hm, const float* __restrict__ stats,
                                         const float* __restrict__ gam, const float* __restrict__ bet,
                                         __half* __restrict__ hi, __half* __restrict__ lo,
                                         int M, int N)
{
    int idx = blockIdx.x * blockDim.x + threadIdx.x;
    if (idx >= M * N) return;
    int col = idx % N;
    float m = stats[col], v = stats[N + col];
    float h = (Hm[idx] - m) * rsqrtf(v + 0.001f) * gam[col] + bet[col];
    h = fmaxf(h, 0.f);
    __half hh = __float2half_rn(h);
    hi[idx] = hh;
    lo[idx] = __float2half_rn(h - __half2float(hh));
}

// ---------------- softmax over 81 classes per row ----------------
__global__ void softmax_kernel(const float* __restrict__ logits, float* __restrict__ probs)
{
    int row = blockIdx.x;
    int t = threadIdx.x;   // 128 threads
    __shared__ float red[128];
    float v = (t < NCLS) ? logits[(size_t)row * NCLS + t] : -INFINITY;
    red[t] = v;
    __syncthreads();
    for (int o = 64; o > 0; o >>= 1) {
        if (t < o) red[t] = fmaxf(red[t], red[t + o]);
        __syncthreads();
    }
    float mx = red[0];
    __syncthreads();
    float e = (t < NCLS) ? expf(v - mx) : 0.f;
    red[t] = e;
    __syncthreads();
    for (int o = 64; o > 0; o >>= 1) {
        if (t < o) red[t] += red[t + o];
        __syncthreads();
    }
    if (t < NCLS) probs[(size_t)row * NCLS + t] = e / red[0];
}

// ---------------- launch ----------------
extern "C" void kernel_launch(void* const* d_in, const int* in_sizes, int n_in,
                              void* d_out, int out_size)
{
    const float* p2      = (const float*)d_in[0];
    const float* p3      = (const float*)d_in[1];
    const float* p4      = (const float*)d_in[2];
    const float* p5      = (const float*)d_in[3];
    const float* rois    = (const float*)d_in[4];
    const float* conv1_w = (const float*)d_in[5];
    const float* conv1_b = (const float*)d_in[6];
    const float* bn1_g   = (const float*)d_in[7];
    const float* bn1_b   = (const float*)d_in[8];
    const float* conv2_w = (const float*)d_in[9];
    const float* conv2_b = (const float*)d_in[10];
    const float* bn2_g   = (const float*)d_in[11];
    const float* bn2_b   = (const float*)d_in[12];
    const float* cls_w   = (const float*)d_in[13];
    const float* cls_b   = (const float*)d_in[14];
    const float* box_w   = (const float*)d_in[15];
    const float* box_b   = (const float*)d_in[16];
    const float* tf1_w   = (const float*)d_in[17];
    const float* tf1_b   = (const float*)d_in[18];
    const float* tf2_w   = (const float*)d_in[19];
    const float* tf2_b   = (const float*)d_in[20];
    float* out = (float*)d_out;

    static __half *xhi=nullptr,*xlo=nullptr,*w1=nullptr,*w2=nullptr,*wcat=nullptr,*hhi=nullptr,*hlo=nullptr;
    static float *hp=nullptr, *sp=nullptr, *st=nullptr, *mw=nullptr, *bcat=nullptr;
    if (!hp) {
        cudaGetSymbolAddress((void**)&xhi, g_xhi);
        cudaGetSymbolAddress((void**)&xlo, g_xlo);
        cudaGetSymbolAddress((void**)&w1, g_w1);
        cudaGetSymbolAddress((void**)&w2, g_w2);
        cudaGetSymbolAddress((void**)&wcat, g_wcat);
        cudaGetSymbolAddress((void**)&bcat, g_bcat);
        cudaGetSymbolAddress((void**)&hhi, g_hhi);
        cudaGetSymbolAddress((void**)&hlo, g_hlo);
        cudaGetSymbolAddress((void**)&hp, g_h);
        cudaGetSymbolAddress((void**)&sp, g_s);
        cudaGetSymbolAddress((void**)&st, g_stats);
        cudaGetSymbolAddress((void**)&mw, g_mw1);
        cudaFuncSetAttribute(gemm_mma2_kernel, cudaFuncAttributeMaxDynamicSharedMemorySize, MM_SMEM);
    }

    const int OFF_LOGITS = 0;
    const int OFF_PROBS  = MROWS * NCLS;                 // 82944
    const int OFF_BBOX   = 2 * MROWS * NCLS;             // 165888
    const int OFF_MW     = OFF_BBOX + MROWS * NCLS * 4;  // 497664

    // 1) ROI align -> xhi/xlo [1024, 12544] (fp16 split)
    roi_align_kernel<<<MROWS, 256>>>(p2, p3, p4, p5, rois, xhi, xlo);

    // weight conversions
    cvt_half_kernel<<<(H1 * K1 + 255) / 256, 256>>>(conv1_w, w1, H1 * K1);
    cvt_half_kernel<<<(H1 * H1 + 255) / 256, 256>>>(conv2_w, w2, H1 * H1);
    build_wcat_kernel<<<(NHEAD * H1 + 255) / 256, 256>>>(cls_w, box_w, cls_b, box_b, wcat, bcat);

    // 2) fc1 (tensor pipe, 2-pass fp16, BK=64): h = x @ conv1_w^T + b
    gemm_mma2_kernel<<<dim3(H1 / MM_BN, MROWS / MM_BM), 256, MM_SMEM>>>(
        xhi, xlo, w1, conv1_b, hp, H1, K1);

    // 3) BN1 + relu -> fp16 split
    bn_stats_kernel<<<H1 / 32, 256>>>(hp, st, MROWS, H1);
    bn_apply_relu_cvt_kernel<<<(MROWS * H1 + 255) / 256, 256>>>(hp, st, bn1_g, bn1_b, hhi, hlo, MROWS, H1);

    // 4) fc2 (tensor pipe): s = h @ conv2_w^T + b
    gemm_mma2_kernel<<<dim3(H1 / MM_BN, MROWS / MM_BM), 256, MM_SMEM>>>(
        hhi, hlo, w2, conv2_b, sp, H1, H1);

    // 5) BN2 + relu -> fp16 split (overwrites hhi/hlo; GEMM2 already consumed them)
    bn_stats_kernel<<<H1 / 32, 256>>>(sp, st, MROWS, H1);
    bn_apply_relu_cvt_kernel<<<(MROWS * H1 + 255) / 256, 256>>>(sp, st, bn2_g, bn2_b, hhi, hlo, MROWS, H1);

    // 6) fused heads (tensor pipe): [logits|bbox|pad] = s @ wcat^T + bcat -> sp
    gemm_mma2_kernel<<<dim3(NHEAD / MM_BN, MROWS / MM_BM), 256, MM_SMEM>>>(
        hhi, hlo, wcat, bcat, sp, NHEAD, H1);
    split_heads_kernel<<<(MROWS * NCLS * 5 + 255) / 256, 256>>>(sp, out + OFF_LOGITS, out + OFF_BBOX);
    softmax_kernel<<<MROWS, 128>>>(out + OFF_LOGITS, out + OFF_PROBS);

    // 7) meta-weight MLP (fp32)
    gemm_abt_kernel<<<dim3(16, 2), 256>>>(cls_w, tf1_w, tf1_b, mw, NCLS, H1, H1, 1);
    gemm_abt_kernel<<<dim3(4, 2), 256>>>(mw, tf2_w, tf2_b, out + OFF_MW, NCLS, 256, H1, 1);
}

// round 17
// speedup vs baseline: 2.5144x; 1.2292x over previous
#include <cuda_runtime.h>
#include <cuda_fp16.h>
#include <math.h>
#include <stdint.h>

#define BB 2
#define NN 512
#define CC 256
#define POOLP 7
#define NCLS 81
#define MROWS (BB*NN)          // 1024
#define K1 (CC*POOLP*POOLP)    // 12544
#define H1 1024
#define IMGSZ 1024.0f
#define NHEAD 512              // padded cls(81)+box(324) rows

// ---------------- scratch (device globals; no allocation allowed) ----------------
__device__ __half g_xhi[(size_t)MROWS * K1];
__device__ __half g_w1[(size_t)H1 * K1];
__device__ __half g_w2[(size_t)H1 * H1];
__device__ __half g_wcat[(size_t)NHEAD * H1];
__device__ float  g_bcat[NHEAD];
__device__ __half g_hhi[(size_t)MROWS * H1];
__device__ __half g_hlo[(size_t)MROWS * H1];
__device__ float g_h[MROWS * H1];           // fc1 pre-BN (fp32)
__device__ float g_s[MROWS * H1];           // fc2 pre-BN / head output scratch
__device__ float g_stats[2 * H1];           // mean, var per feature
__device__ float g_mw1[NCLS * H1];          // MLP intermediate

// ================= PTX helpers (base-target only: sm_80-class) =================
__device__ __forceinline__ uint32_t smem_u32(const void* p) {
    uint32_t a;
    asm("{ .reg .u64 t; cvta.to.shared.u64 t, %1; cvt.u32.u64 %0, t; }" : "=r"(a) : "l"(p));
    return a;
}
__device__ __forceinline__ void cp_async16(uint32_t dst, const void* src) {
    asm volatile("cp.async.cg.shared.global [%0], [%1], 16;" :: "r"(dst), "l"(src) : "memory");
}
__device__ __forceinline__ void ldsm_x4(uint32_t* r, uint32_t addr) {
    asm volatile("ldmatrix.sync.aligned.m8n8.x4.shared.b16 {%0,%1,%2,%3}, [%4];"
                 : "=r"(r[0]), "=r"(r[1]), "=r"(r[2]), "=r"(r[3]) : "r"(addr));
}
__device__ __forceinline__ void mma16816(float* d, const uint32_t* a, const uint32_t* b) {
    asm volatile("mma.sync.aligned.m16n8k16.row.col.f32.f16.f16.f32 "
                 "{%0,%1,%2,%3}, {%4,%5,%6,%7}, {%8,%9}, {%0,%1,%2,%3};"
                 : "+f"(d[0]), "+f"(d[1]), "+f"(d[2]), "+f"(d[3])
                 : "r"(a[0]), "r"(a[1]), "r"(a[2]), "r"(a[3]), "r"(b[0]), "r"(b[1]));
}

// ====== mma.sync fp16 GEMM (SPLIT-pass A): C = (sum_s A_s)[M,K] @ B[N,K]^T + bias
// SPLIT=1: A single fp16. SPLIT=2: A = Ahi + Alo (~22-bit effective).
// Requires M % 64 == 0, N % 128 == 0, K % 64 == 0.
#define MM_BM 64
#define MM_BN 128
#define MM_BK 64
#define MM_RSTRIDE 144                  // bytes per smem row (64 fp16 + 16B pad)
#define MM_ABYTES (MM_BM * MM_RSTRIDE)  // 9216
#define MM_BBYTES (MM_BN * MM_RSTRIDE)  // 18432
#define MM_STAGES 3

template<int SPLIT>
__global__ void __launch_bounds__(256, 1)
gemm_fp16_kernel(const __half* __restrict__ Ahi, const __half* __restrict__ Alo,
                 const __half* __restrict__ Bf,
                 const float* __restrict__ bias, float* __restrict__ C, int N, int K)
{
    constexpr uint32_t BUF = (uint32_t)SPLIT * MM_ABYTES + MM_BBYTES;
    extern __shared__ char smem[];
    uint32_t sb = smem_u32(smem);
    int tid = threadIdx.x;
    int wid = tid >> 5, lane = tid & 31;
    int rowBase = blockIdx.y * MM_BM;
    int colBase = blockIdx.x * MM_BN;
    int warp_m = wid >> 2;      // 0..1  -> 32 rows each
    int warp_n = wid & 3;       // 0..3  -> 32 cols each
    int m_base = warp_m * 32;
    int n_base = warp_n * 32;

    float acc[2][4][4];
    #pragma unroll
    for (int mt = 0; mt < 2; mt++)
        #pragma unroll
        for (int nt = 0; nt < 4; nt++)
            #pragma unroll
            for (int j = 0; j < 4; j++) acc[mt][nt][j] = 0.f;

    int nc = K / MM_BK;

    auto load_chunk = [&](int c, int slot) {
        uint32_t base = sb + (uint32_t)slot * BUF;
        int k0 = c * MM_BK;
        #pragma unroll
        for (int i = 0; i < 2 * SPLIT; i++) {         // A: SPLIT*512 x 16B segments
            int id = tid + i * 256;
            int t = id >> 9;                          // 0=hi 1=lo
            int s = id & 511;
            int r = s >> 3, cseg = s & 7;
            const __half* src = (t ? Alo : Ahi) + (size_t)(rowBase + r) * K + k0 + cseg * 8;
            cp_async16(base + (uint32_t)t * MM_ABYTES + (uint32_t)(r * MM_RSTRIDE + cseg * 16), src);
        }
        #pragma unroll
        for (int i = 0; i < 4; i++) {                 // B: 1024 x 16B segments
            int id = tid + i * 256;
            int r = id >> 3, cseg = id & 7;
            const __half* src = Bf + (size_t)(colBase + r) * K + k0 + cseg * 8;
            cp_async16(base + (uint32_t)SPLIT * MM_ABYTES + (uint32_t)(r * MM_RSTRIDE + cseg * 16), src);
        }
        asm volatile("cp.async.commit_group;" ::: "memory");
    };

    // prologue: 2-deep prefetch
    load_chunk(0, 0);
    load_chunk(1, 1);

    // hoisted fragment address components
    int arow = m_base + (lane & 15);
    uint32_t acol_base = (uint32_t)(((lane >> 4) << 3) * 2);
    int brow = n_base + ((lane >= 16) ? 8 : 0) + (lane & 7);
    uint32_t bcol_base = (uint32_t)((((lane >> 3) & 1) << 3) * 2);

    for (int c = 0; c < nc; c++) {
        if (c + 1 < nc) {
            asm volatile("cp.async.wait_group 1;" ::: "memory");
        } else {
            asm volatile("cp.async.wait_group 0;" ::: "memory");
        }
        __syncthreads();

        if (c + 2 < nc) load_chunk(c + 2, (c + 2) % MM_STAGES);

        uint32_t abase = sb + (uint32_t)(c % MM_STAGES) * BUF;
        uint32_t bbase = abase + (uint32_t)SPLIT * MM_ABYTES;

        #pragma unroll
        for (int kh = 0; kh < 2; kh++) {
            uint32_t af[SPLIT][2][2][4];           // [sp][ks][mt][4]
            uint32_t bfr[2][4][2];                 // [ks][nt][2]
            #pragma unroll
            for (int ks = 0; ks < 2; ks++) {
                uint32_t acol = acol_base + (uint32_t)(kh * 64 + ks * 32);
                #pragma unroll
                for (int mt = 0; mt < 2; mt++) {
                    uint32_t addr = abase + (uint32_t)((arow + mt * 16) * MM_RSTRIDE) + acol;
                    #pragma unroll
                    for (int sp = 0; sp < SPLIT; sp++)
                        ldsm_x4(af[sp][ks][mt], addr + (uint32_t)sp * MM_ABYTES);
                }
                uint32_t bcol = bcol_base + (uint32_t)(kh * 64 + ks * 32);
                #pragma unroll
                for (int np = 0; np < 2; np++) {
                    uint32_t addr = bbase + (uint32_t)((brow + np * 16) * MM_RSTRIDE) + bcol;
                    uint32_t r4[4];
                    ldsm_x4(r4, addr);
                    bfr[ks][np*2][0] = r4[0]; bfr[ks][np*2][1] = r4[1];
                    bfr[ks][np*2+1][0] = r4[2]; bfr[ks][np*2+1][1] = r4[3];
                }
            }
            #pragma unroll
            for (int ks = 0; ks < 2; ks++)
                #pragma unroll
                for (int sp = 0; sp < SPLIT; sp++)
                    #pragma unroll
                    for (int mt = 0; mt < 2; mt++)
                        #pragma unroll
                        for (int nt = 0; nt < 4; nt++)
                            mma16816(acc[mt][nt], af[sp][ks][mt], bfr[ks][nt]);
        }
    }

    // ---- epilogue: bias + store ----
    int g = lane >> 2, t2 = (lane & 3) * 2;
    #pragma unroll
    for (int mt = 0; mt < 2; mt++) {
        int row0 = rowBase + m_base + mt * 16 + g;
        #pragma unroll
        for (int nt = 0; nt < 4; nt++) {
            int col = colBase + n_base + nt * 8 + t2;
            float b0 = bias[col], b1 = bias[col + 1];
            float2* p0 = reinterpret_cast<float2*>(&C[(size_t)row0 * N + col]);
            float2* p1 = reinterpret_cast<float2*>(&C[(size_t)(row0 + 8) * N + col]);
            *p0 = make_float2(acc[mt][nt][0] + b0, acc[mt][nt][1] + b1);
            *p1 = make_float2(acc[mt][nt][2] + b0, acc[mt][nt][3] + b1);
        }
    }
}

// ---------------- ROI align -> fp16 (single) ----------------
__global__ void roi_align_kernel(const float* __restrict__ p2, const float* __restrict__ p3,
                                 const float* __restrict__ p4, const float* __restrict__ p5,
                                 const float* __restrict__ rois,
                                 __half* __restrict__ Xhi)
{
    int n = blockIdx.x;
    const float* roi = rois + (size_t)n * 4;
    float x1 = roi[0], y1 = roi[1], x2 = roi[2], y2 = roi[3];
    float area = (y2 - y1) * (x2 - x1);
    float lf = rintf(log2f(sqrtf(area) / 224.0f)) + 4.0f;   // half-to-even like jnp.round
    lf = fminf(fmaxf(lf, 2.0f), 5.0f);
    int lvl = (int)lf;

    const float* fm; int H;
    if (lvl == 2)      { fm = p2; H = 256; }
    else if (lvl == 3) { fm = p3; H = 128; }
    else if (lvl == 4) { fm = p4; H = 64;  }
    else               { fm = p5; H = 32;  }
    int W = H;

    float ny1 = y1 / IMGSZ, nx1 = x1 / IMGSZ, ny2 = y2 / IMGSZ, nx2 = x2 / IMGSZ;

    __shared__ int   s_y0[POOLP], s_y1[POOLP], s_x0[POOLP], s_x1[POOLP];
    __shared__ float s_ly[POOLP], s_lx[POOLP];

    int t = threadIdx.x;
    if (t < POOLP) {
        float g = (float)t / (float)(POOLP - 1);
        float ys = (ny1 + g * (ny2 - ny1)) * (float)(H - 1);
        float y0f = floorf(ys);
        s_ly[t] = ys - y0f;
        s_y0[t] = (int)fminf(fmaxf(y0f, 0.0f), (float)(H - 1));
        s_y1[t] = (int)fminf(fmaxf(y0f + 1.0f, 0.0f), (float)(H - 1));
    } else if (t < 2 * POOLP) {
        int j = t - POOLP;
        float g = (float)j / (float)(POOLP - 1);
        float xs = (nx1 + g * (nx2 - nx1)) * (float)(W - 1);
        float x0f = floorf(xs);
        s_lx[j] = xs - x0f;
        s_x0[j] = (int)fminf(fmaxf(x0f, 0.0f), (float)(W - 1));
        s_x1[j] = (int)fminf(fmaxf(x0f + 1.0f, 0.0f), (float)(W - 1));
    }
    __syncthreads();

    int HW = H * W;
    for (int idx = threadIdx.x; idx < K1; idx += blockDim.x) {
        int c  = idx / (POOLP * POOLP);
        int p  = idx % (POOLP * POOLP);
        int py = p / POOLP, px = p % POOLP;
        const float* plane = fm + (size_t)c * HW;
        float ly = s_ly[py], lx = s_lx[px];
        int y0 = s_y0[py], y1i = s_y1[py], x0 = s_x0[px], x1i = s_x1[px];
        float v00 = plane[y0  * W + x0 ];
        float v01 = plane[y0  * W + x1i];
        float v10 = plane[y1i * W + x0 ];
        float v11 = plane[y1i * W + x1i];
        float val = v00 * (1.0f - ly) * (1.0f - lx)
                  + v01 * (1.0f - ly) * lx
                  + v10 * ly * (1.0f - lx)
                  + v11 * ly * lx;
        Xhi[(size_t)n * K1 + idx] = __float2half_rn(val);
    }
}

// ---------------- fp32 -> fp16 single ----------------
__global__ void cvt_half_kernel(const float* __restrict__ src, __half* __restrict__ dst, int n)
{
    int i = blockIdx.x * blockDim.x + threadIdx.x;
    if (i < n) dst[i] = __float2half_rn(src[i]);
}

// ---------------- build padded concat head weights (cls 81 + box 324 + 0-pad) --
__global__ void build_wcat_kernel(const float* __restrict__ cls_w, const float* __restrict__ box_w,
                                  const float* __restrict__ cls_b, const float* __restrict__ box_b,
                                  __half* __restrict__ wcat, float* __restrict__ bcat)
{
    int idx = blockIdx.x * blockDim.x + threadIdx.x;
    if (idx >= NHEAD * H1) return;
    int r = idx >> 10, k = idx & (H1 - 1);
    float v = 0.f;
    if (r < NCLS) v = cls_w[r * H1 + k];
    else if (r < NCLS * 5) v = box_w[(r - NCLS) * H1 + k];
    wcat[idx] = __float2half_rn(v);
    if (k == 0) bcat[r] = (r < NCLS) ? cls_b[r] : ((r < NCLS * 5) ? box_b[r - NCLS] : 0.f);
}

// ---------------- split head output into logits / bbox ----------------
__global__ void split_heads_kernel(const float* __restrict__ C, float* __restrict__ logits,
                                   float* __restrict__ bbox)
{
    int idx = blockIdx.x * blockDim.x + threadIdx.x;
    if (idx >= MROWS * NCLS * 5) return;          // 405 per row
    int row = idx / (NCLS * 5), c = idx % (NCLS * 5);
    float v = C[(size_t)row * NHEAD + c];
    if (c < NCLS) logits[(size_t)row * NCLS + c] = v;
    else          bbox[(size_t)row * NCLS * 4 + (c - NCLS)] = v;
}

// ---------------- fp32 tiled GEMM for small MLP: C = A @ B^T + bias ----------------
#define BM 64
#define BN 64
#define BK 16
__global__ void gemm_abt_kernel(const float* __restrict__ A, const float* __restrict__ B,
                                const float* __restrict__ bias, float* __restrict__ C,
                                int M, int N, int K, int act)
{
    __shared__ float As[BK][BM];
    __shared__ float Bs[BK][BN];

    int tid = threadIdx.x;
    int tx = tid & 15;
    int ty = tid >> 4;
    int rowBase = blockIdx.y * BM;
    int colBase = blockIdx.x * BN;
    int lr = tid >> 2;
    int lk = (tid & 3) * 4;

    float acc[4][4] = {{0.f}};

    for (int k0 = 0; k0 < K; k0 += BK) {
        float4 av = make_float4(0.f, 0.f, 0.f, 0.f);
        int ar = rowBase + lr;
        if (ar < M) av = *reinterpret_cast<const float4*>(&A[(size_t)ar * K + k0 + lk]);
        As[lk + 0][lr] = av.x; As[lk + 1][lr] = av.y;
        As[lk + 2][lr] = av.z; As[lk + 3][lr] = av.w;

        float4 bv = make_float4(0.f, 0.f, 0.f, 0.f);
        int br = colBase + lr;
        if (br < N) bv = *reinterpret_cast<const float4*>(&B[(size_t)br * K + k0 + lk]);
        Bs[lk + 0][lr] = bv.x; Bs[lk + 1][lr] = bv.y;
        Bs[lk + 2][lr] = bv.z; Bs[lk + 3][lr] = bv.w;

        __syncthreads();

        #pragma unroll
        for (int k = 0; k < BK; k++) {
            float4 a = *reinterpret_cast<const float4*>(&As[k][ty * 4]);
            float4 b = *reinterpret_cast<const float4*>(&Bs[k][tx * 4]);
            float aa[4] = {a.x, a.y, a.z, a.w};
            float bb[4] = {b.x, b.y, b.z, b.w};
            #pragma unroll
            for (int i = 0; i < 4; i++)
                #pragma unroll
                for (int j = 0; j < 4; j++)
                    acc[i][j] = fmaf(aa[i], bb[j], acc[i][j]);
        }
        __syncthreads();
    }

    #pragma unroll
    for (int i = 0; i < 4; i++) {
        int row = rowBase + ty * 4 + i;
        if (row >= M) continue;
        #pragma unroll
        for (int j = 0; j < 4; j++) {
            int col = colBase + tx * 4 + j;
            if (col >= N) continue;
            float v = acc[i][j] + bias[col];
            if (act == 1) v = (v >= 0.f) ? v : 0.01f * v;
            C[(size_t)row * N + col] = v;
        }
    }
}

// ---------------- batch-norm stats (coalesced: 32 cols x 8 rows per block) ----------------
__global__ void bn_stats_kernel(const float* __restrict__ Hm, float* __restrict__ stats,
                                int M, int N)
{
    int x = threadIdx.x & 31, y = threadIdx.x >> 5;   // 256 threads
    int col = blockIdx.x * 32 + x;
    float s = 0.f, s2 = 0.f;
    for (int r = y; r < M; r += 8) {
        float v = Hm[(size_t)r * N + col];
        s += v; s2 += v * v;
    }
    __shared__ float sh[8][32], sh2[8][32];
    sh[y][x] = s; sh2[y][x] = s2;
    __syncthreads();
    if (y == 0) {
        #pragma unroll
        for (int i = 1; i < 8; i++) { s += sh[i][x]; s2 += sh2[i][x]; }
        float m = s / (float)M;
        stats[col]     = m;
        stats[N + col] = s2 / (float)M - m * m;
    }
}

// BN apply + relu, write fp16 hi/lo (feeds fp16 GEMMs)
__global__ void bn_apply_relu_cvt_kernel(const float* __restrict__ Hm, const float* __restrict__ stats,
                                         const float* __restrict__ gam, const float* __restrict__ bet,
                                         __half* __restrict__ hi, __half* __restrict__ lo,
                                         int M, int N)
{
    int idx = blockIdx.x * blockDim.x + threadIdx.x;
    if (idx >= M * N) return;
    int col = idx % N;
    float m = stats[col], v = stats[N + col];
    float h = (Hm[idx] - m) * rsqrtf(v + 0.001f) * gam[col] + bet[col];
    h = fmaxf(h, 0.f);
    __half hh = __float2half_rn(h);
    hi[idx] = hh;
    lo[idx] = __float2half_rn(h - __half2float(hh));
}

// ---------------- softmax over 81 classes per row ----------------
__global__ void softmax_kernel(const float* __restrict__ logits, float* __restrict__ probs)
{
    int row = blockIdx.x;
    int t = threadIdx.x;   // 128 threads
    __shared__ float red[128];
    float v = (t < NCLS) ? logits[(size_t)row * NCLS + t] : -INFINITY;
    red[t] = v;
    __syncthreads();
    for (int o = 64; o > 0; o >>= 1) {
        if (t < o) red[t] = fmaxf(red[t], red[t + o]);
        __syncthreads();
    }
    float mx = red[0];
    __syncthreads();
    float e = (t < NCLS) ? expf(v - mx) : 0.f;
    red[t] = e;
    __syncthreads();
    for (int o = 64; o > 0; o >>= 1) {
        if (t < o) red[t] += red[t + o];
        __syncthreads();
    }
    if (t < NCLS) probs[(size_t)row * NCLS + t] = e / red[0];
}

// ---------------- launch ----------------
extern "C" void kernel_launch(void* const* d_in, const int* in_sizes, int n_in,
                              void* d_out, int out_size)
{
    const float* p2      = (const float*)d_in[0];
    const float* p3      = (const float*)d_in[1];
    const float* p4      = (const float*)d_in[2];
    const float* p5      = (const float*)d_in[3];
    const float* rois    = (const float*)d_in[4];
    const float* conv1_w = (const float*)d_in[5];
    const float* conv1_b = (const float*)d_in[6];
    const float* bn1_g   = (const float*)d_in[7];
    const float* bn1_b   = (const float*)d_in[8];
    const float* conv2_w = (const float*)d_in[9];
    const float* conv2_b = (const float*)d_in[10];
    const float* bn2_g   = (const float*)d_in[11];
    const float* bn2_b   = (const float*)d_in[12];
    const float* cls_w   = (const float*)d_in[13];
    const float* cls_b   = (const float*)d_in[14];
    const float* box_w   = (const float*)d_in[15];
    const float* box_b   = (const float*)d_in[16];
    const float* tf1_w   = (const float*)d_in[17];
    const float* tf1_b   = (const float*)d_in[18];
    const float* tf2_w   = (const float*)d_in[19];
    const float* tf2_b   = (const float*)d_in[20];
    float* out = (float*)d_out;

    static __half *xhi=nullptr,*w1=nullptr,*w2=nullptr,*wcat=nullptr,*hhi=nullptr,*hlo=nullptr;
    static float *hp=nullptr, *sp=nullptr, *st=nullptr, *mw=nullptr, *bcat=nullptr;
    if (!hp) {
        cudaGetSymbolAddress((void**)&xhi, g_xhi);
        cudaGetSymbolAddress((void**)&w1, g_w1);
        cudaGetSymbolAddress((void**)&w2, g_w2);
        cudaGetSymbolAddress((void**)&wcat, g_wcat);
        cudaGetSymbolAddress((void**)&bcat, g_bcat);
        cudaGetSymbolAddress((void**)&hhi, g_hhi);
        cudaGetSymbolAddress((void**)&hlo, g_hlo);
        cudaGetSymbolAddress((void**)&hp, g_h);
        cudaGetSymbolAddress((void**)&sp, g_s);
        cudaGetSymbolAddress((void**)&st, g_stats);
        cudaGetSymbolAddress((void**)&mw, g_mw1);
        cudaFuncSetAttribute(gemm_fp16_kernel<1>, cudaFuncAttributeMaxDynamicSharedMemorySize,
                             MM_STAGES * (1 * MM_ABYTES + MM_BBYTES));
        cudaFuncSetAttribute(gemm_fp16_kernel<2>, cudaFuncAttributeMaxDynamicSharedMemorySize,
                             MM_STAGES * (2 * MM_ABYTES + MM_BBYTES));
    }

    const int SMEM1 = MM_STAGES * (1 * MM_ABYTES + MM_BBYTES);   // 82944
    const int SMEM2 = MM_STAGES * (2 * MM_ABYTES + MM_BBYTES);   // 110592

    const int OFF_LOGITS = 0;
    const int OFF_PROBS  = MROWS * NCLS;                 // 82944
    const int OFF_BBOX   = 2 * MROWS * NCLS;             // 165888
    const int OFF_MW     = OFF_BBOX + MROWS * NCLS * 4;  // 497664

    // 1) ROI align -> xhi [1024, 12544] (fp16)
    roi_align_kernel<<<MROWS, 256>>>(p2, p3, p4, p5, rois, xhi);

    // weight conversions
    cvt_half_kernel<<<(H1 * K1 + 255) / 256, 256>>>(conv1_w, w1, H1 * K1);
    cvt_half_kernel<<<(H1 * H1 + 255) / 256, 256>>>(conv2_w, w2, H1 * H1);
    build_wcat_kernel<<<(NHEAD * H1 + 255) / 256, 256>>>(cls_w, box_w, cls_b, box_b, wcat, bcat);

    // 2) fc1 (tensor pipe, single-pass fp16): h = x @ conv1_w^T + b
    gemm_fp16_kernel<1><<<dim3(H1 / MM_BN, MROWS / MM_BM), 256, SMEM1>>>(
        xhi, xhi, w1, conv1_b, hp, H1, K1);

    // 3) BN1 + relu -> fp16 split
    bn_stats_kernel<<<H1 / 32, 256>>>(hp, st, MROWS, H1);
    bn_apply_relu_cvt_kernel<<<(MROWS * H1 + 255) / 256, 256>>>(hp, st, bn1_g, bn1_b, hhi, hlo, MROWS, H1);

    // 4) fc2 (tensor pipe, 2-pass): s = h @ conv2_w^T + b
    gemm_fp16_kernel<2><<<dim3(H1 / MM_BN, MROWS / MM_BM), 256, SMEM2>>>(
        hhi, hlo, w2, conv2_b, sp, H1, H1);

    // 5) BN2 + relu -> fp16 split (reuse hhi/hlo)
    bn_stats_kernel<<<H1 / 32, 256>>>(sp, st, MROWS, H1);
    bn_apply_relu_cvt_kernel<<<(MROWS * H1 + 255) / 256, 256>>>(sp, st, bn2_g, bn2_b, hhi, hlo, MROWS, H1);

    // 6) fused heads (tensor pipe, 2-pass): [logits|bbox|pad] = s @ wcat^T + bcat
    gemm_fp16_kernel<2><<<dim3(NHEAD / MM_BN, MROWS / MM_BM), 256, SMEM2>>>(
        hhi, hlo, wcat, bcat, sp, NHEAD, H1);
    split_heads_kernel<<<(MROWS * NCLS * 5 + 255) / 256, 256>>>(sp, out + OFF_LOGITS, out + OFF_BBOX);
    softmax_kernel<<<MROWS, 128>>>(out + OFF_LOGITS, out + OFF_PROBS);

    // 7) meta-weight MLP (fp32)
    gemm_abt_kernel<<<dim3(16, 2), 256>>>(cls_w, tf1_w, tf1_b, mw, NCLS, H1, H1, 1);
    gemm_abt_kernel<<<dim3(4, 2), 256>>>(mw, tf2_w, tf2_b, out + OFF_MW, NCLS, 256, H1, 1);
}